// round 4
// baseline (speedup 1.0000x reference)
#include <cuda_runtime.h>
#include <math.h>
#include <stdint.h>

#define Bq 2
#define Lq 2048
#define Dq 768
#define Hq 12
#define ROWS (Bq*Lq)   /* 4096 */

// ---------------- scratch (device globals; no allocation allowed) ----------------
__device__ float g_t1[(size_t)ROWS*3072];
__device__ float g_p [(size_t)ROWS*1024];
__device__ float g_ha[(size_t)ROWS*Dq];
__device__ float g_hb[(size_t)ROWS*Dq];
__device__ float g_x [(size_t)ROWS*Dq];
__device__ float g_qk[(size_t)ROWS*Dq];
__device__ float g_q [(size_t)ROWS*Dq];
__device__ float g_k [(size_t)ROWS*Dq];
__device__ float g_v [(size_t)ROWS*Dq];
__device__ float g_att[(size_t)ROWS*Dq];
__device__ float g_o [(size_t)ROWS*Dq];
__device__ float g_x2[(size_t)ROWS*Dq];

__device__ __forceinline__ float gelu_f(float x){
    return 0.5f*x*(1.0f+erff(x*0.70710678118654752440f));
}

// TF32 rounding (matches cuBLAS/cutlass input conversion for TF32 GEMMs)
__device__ __forceinline__ float tf32r(float x){
    uint32_t u;
    asm("cvt.rna.tf32.f32 %0, %1;" : "=r"(u) : "f"(x));
    return __uint_as_float(u);
}

// ---------------- generic 128x128 tiled GEMM in TF32-emulation:
// inputs rounded to tf32, products exact, fp32 accumulate. C = A@B + bias [,GELU][,+Res]
template<int GELU, int RES>
__global__ void __launch_bounds__(256) sgemm128(
    const float* __restrict__ A, const float* __restrict__ Bm,
    const float* __restrict__ bias, const float* __restrict__ Rr,
    float* __restrict__ C, int N, int K)
{
    __shared__ float As[8][128];
    __shared__ float Bs[8][128];
    const int tid = threadIdx.x;
    const int row0 = blockIdx.y * 128;
    const int col0 = blockIdx.x * 128;
    const int tx = tid & 15, ty = tid >> 4;
    const int lam = tid >> 1, lak = (tid & 1) * 4;
    const int lbk = tid >> 5, lbn = (tid & 31) * 4;
    const bool colFull = (col0 + 128 <= N);

    float acc[8][8];
    #pragma unroll
    for (int i = 0; i < 8; i++)
        #pragma unroll
        for (int j = 0; j < 8; j++) acc[i][j] = 0.f;

    for (int k0 = 0; k0 < K; k0 += 8) {
        float4 av = *(const float4*)(A + (size_t)(row0 + lam) * K + k0 + lak);
        As[lak+0][lam] = tf32r(av.x); As[lak+1][lam] = tf32r(av.y);
        As[lak+2][lam] = tf32r(av.z); As[lak+3][lam] = tf32r(av.w);
        if (colFull) {
            float4 bv = *(const float4*)(Bm + (size_t)(k0 + lbk) * N + col0 + lbn);
            Bs[lbk][lbn+0] = tf32r(bv.x); Bs[lbk][lbn+1] = tf32r(bv.y);
            Bs[lbk][lbn+2] = tf32r(bv.z); Bs[lbk][lbn+3] = tf32r(bv.w);
        } else {
            #pragma unroll
            for (int u = 0; u < 4; u++) {
                int c = col0 + lbn + u;
                Bs[lbk][lbn+u] = (c < N) ? tf32r(Bm[(size_t)(k0 + lbk) * N + c]) : 0.f;
            }
        }
        __syncthreads();
        #pragma unroll
        for (int kk = 0; kk < 8; kk++) {
            float4 a0 = *(const float4*)&As[kk][ty*4];
            float4 a1 = *(const float4*)&As[kk][64 + ty*4];
            float4 b0 = *(const float4*)&Bs[kk][tx*4];
            float4 b1 = *(const float4*)&Bs[kk][64 + tx*4];
            float a[8] = {a0.x,a0.y,a0.z,a0.w,a1.x,a1.y,a1.z,a1.w};
            float b[8] = {b0.x,b0.y,b0.z,b0.w,b1.x,b1.y,b1.z,b1.w};
            #pragma unroll
            for (int i = 0; i < 8; i++)
                #pragma unroll
                for (int j = 0; j < 8; j++)
                    acc[i][j] = fmaf(a[i], b[j], acc[i][j]);
        }
        __syncthreads();
    }

    #pragma unroll
    for (int i = 0; i < 8; i++) {
        int r = row0 + ((i < 4) ? (ty*4 + i) : (64 + ty*4 + i - 4));
        #pragma unroll
        for (int j = 0; j < 8; j++) {
            int c = col0 + ((j < 4) ? (tx*4 + j) : (64 + tx*4 + j - 4));
            if (c < N) {
                float v = acc[i][j] + bias[c];
                if (GELU) v = gelu_f(v);
                if (RES)  v += Rr[(size_t)r * N + c];
                C[(size_t)r * N + c] = v;
            }
        }
    }
}

// ---------------- data-dependent causal conv + GELU (fp32, reference scan order)
__global__ void conv_gelu(const float* __restrict__ h, const float* __restrict__ p,
                          float* __restrict__ out, int F, int pstride, int poff)
{
    int idx = blockIdx.x * blockDim.x + threadIdx.x;
    if (idx >= ROWS * (Dq/4)) return;
    int d4 = idx % (Dq/4);
    int bt = idx / (Dq/4);
    int t  = bt & (Lq - 1);
    const float* kr = p + (size_t)bt * pstride + poff;
    int mmax = min(F - 1, t);
    float ax = 0.f, ay = 0.f, az = 0.f, aw = 0.f;
    for (int m = mmax; m >= 0; --m) {   // j ascending in reference scan
        float kv = __ldg(kr + m);
        const float4 hv = *(const float4*)(h + (size_t)(bt - m) * Dq + d4 * 4);
        ax = fmaf(kv, hv.x, ax);
        ay = fmaf(kv, hv.y, ay);
        az = fmaf(kv, hv.z, az);
        aw = fmaf(kv, hv.w, aw);
    }
    float4 o;
    o.x = gelu_f(ax); o.y = gelu_f(ay); o.z = gelu_f(az); o.w = gelu_f(aw);
    *(float4*)(out + (size_t)bt * Dq + d4 * 4) = o;
}

// ---------------- LayerNorm of (a+b): two-pass, fp64 accumulators
__global__ void ln_kernel(const float* __restrict__ a, const float* __restrict__ b,
                          const float* __restrict__ g, const float* __restrict__ be,
                          float* __restrict__ out)
{
    __shared__ double red[10];
    int row = blockIdx.x, tid = threadIdx.x;
    const float* pa = a + (size_t)row * Dq;
    const float* pb = b + (size_t)row * Dq;
    float v[3];
    double s = 0.0;
    #pragma unroll
    for (int i = 0; i < 3; i++) {
        float x = pa[tid + 256*i] + pb[tid + 256*i];
        v[i] = x; s += (double)x;
    }
    #pragma unroll
    for (int o = 16; o; o >>= 1) s += __shfl_down_sync(0xffffffffu, s, o);
    if ((tid & 31) == 0) red[tid >> 5] = s;
    __syncthreads();
    if (tid == 0) {
        double t = 0.0;
        #pragma unroll
        for (int w = 0; w < 8; w++) t += red[w];
        red[8] = t * (1.0/768.0);
    }
    __syncthreads();
    float mean = (float)red[8];

    double s2 = 0.0;
    #pragma unroll
    for (int i = 0; i < 3; i++) {
        double d = (double)v[i] - red[8];
        s2 += d * d;
    }
    #pragma unroll
    for (int o = 16; o; o >>= 1) s2 += __shfl_down_sync(0xffffffffu, s2, o);
    if ((tid & 31) == 0) red[tid >> 5] = s2;
    __syncthreads();
    if (tid == 0) {
        double t = 0.0;
        #pragma unroll
        for (int w = 0; w < 8; w++) t += red[w];
        red[9] = 1.0 / sqrt(t * (1.0/768.0) + 1e-5);
    }
    __syncthreads();
    float rs = (float)red[9];
    #pragma unroll
    for (int i = 0; i < 3; i++) {
        int c = tid + 256*i;
        out[(size_t)row * Dq + c] = (v[i] - mean) * rs * g[c] + be[c];
    }
}

// ---------------- RoPE
__global__ void rope_kernel(const float* __restrict__ x, const float* __restrict__ sn,
                            const float* __restrict__ cs, float* __restrict__ out)
{
    int idx = blockIdx.x * blockDim.x + threadIdx.x;
    if (idx >= ROWS * 384) return;
    int d = idx % 384, row = idx / 384, l = row & (Lq - 1);
    float x1 = x[(size_t)row * Dq + d];
    float x2 = x[(size_t)row * Dq + 384 + d];
    float sv = sn[l * 384 + d], cv = cs[l * 384 + d];
    out[(size_t)row * Dq + d]        = x1 * cv - x2 * sv;
    out[(size_t)row * Dq + 384 + d]  = x2 * cv + x1 * sv;
}

// ---------------- fused flash-style attention, hd=64, TF32-emulated dot products
#define AP 65
#define ATT_SMEM (3*64*AP*4)
__global__ void __launch_bounds__(256) attn_kernel(
    const float* __restrict__ Q, const float* __restrict__ K,
    const float* __restrict__ V, float* __restrict__ O)
{
    extern __shared__ float sm[];
    float* Qs = sm;              // 64 x AP, tf32-rounded (unscaled)
    float* KP = sm + 64*AP;      // K tile (tf32), reused as P tile (tf32)
    float* Vs = sm + 2*64*AP;    // V tile (tf32)
    int tid = threadIdx.x;
    int bh = blockIdx.y;
    int b = bh / Hq, h = bh % Hq;
    int q0 = blockIdx.x * 64;
    size_t base = (size_t)b * Lq * Dq + (size_t)h * 64;

    for (int i = tid; i < 64*16; i += 256) {
        int rr = i >> 4, c4 = (i & 15) * 4;
        float4 qv = *(const float4*)(Q + base + (size_t)(q0 + rr) * Dq + c4);
        Qs[rr*AP + c4+0] = tf32r(qv.x);
        Qs[rr*AP + c4+1] = tf32r(qv.y);
        Qs[rr*AP + c4+2] = tf32r(qv.z);
        Qs[rr*AP + c4+3] = tf32r(qv.w);
    }

    int r = tid >> 2, cg = tid & 3;
    float m_i = -INFINITY, l_i = 0.f;
    float o[16];
    #pragma unroll
    for (int j = 0; j < 16; j++) o[j] = 0.f;

    for (int kt = 0; kt < Lq/64; ++kt) {
        __syncthreads();
        for (int i = tid; i < 64*16; i += 256) {
            int rr = i >> 4, c4 = (i & 15) * 4;
            float4 kv = *(const float4*)(K + base + (size_t)(kt*64 + rr) * Dq + c4);
            KP[rr*AP + c4+0] = tf32r(kv.x); KP[rr*AP + c4+1] = tf32r(kv.y);
            KP[rr*AP + c4+2] = tf32r(kv.z); KP[rr*AP + c4+3] = tf32r(kv.w);
            float4 vv = *(const float4*)(V + base + (size_t)(kt*64 + rr) * Dq + c4);
            Vs[rr*AP + c4+0] = tf32r(vv.x); Vs[rr*AP + c4+1] = tf32r(vv.y);
            Vs[rr*AP + c4+2] = tf32r(vv.z); Vs[rr*AP + c4+3] = tf32r(vv.w);
        }
        __syncthreads();

        float s[16];
        #pragma unroll
        for (int j = 0; j < 16; j++) s[j] = 0.f;
        #pragma unroll 4
        for (int d = 0; d < 64; ++d) {
            float qd = Qs[r*AP + d];
            #pragma unroll
            for (int j = 0; j < 16; j++)
                s[j] = fmaf(qd, KP[(cg*16 + j)*AP + d], s[j]);
        }
        #pragma unroll
        for (int j = 0; j < 16; j++) s[j] *= 0.125f;  // scale after dot, like reference

        float mx = s[0];
        #pragma unroll
        for (int j = 1; j < 16; j++) mx = fmaxf(mx, s[j]);
        mx = fmaxf(mx, __shfl_xor_sync(0xffffffffu, mx, 1));
        mx = fmaxf(mx, __shfl_xor_sync(0xffffffffu, mx, 2));
        float m_new = fmaxf(m_i, mx);
        float ps = 0.f;
        #pragma unroll
        for (int j = 0; j < 16; j++) { s[j] = expf(s[j] - m_new); ps += s[j]; }
        ps += __shfl_xor_sync(0xffffffffu, ps, 1);
        ps += __shfl_xor_sync(0xffffffffu, ps, 2);
        float alpha = expf(m_i - m_new);
        l_i = l_i * alpha + ps;
        m_i = m_new;
        #pragma unroll
        for (int j = 0; j < 16; j++) o[j] *= alpha;

        __syncthreads();
        #pragma unroll
        for (int j = 0; j < 16; j++) KP[r*AP + cg*16 + j] = tf32r(s[j]);
        __syncthreads();

        #pragma unroll 4
        for (int k = 0; k < 64; k++) {
            float pv = KP[r*AP + k];
            const float* vrow = &Vs[k*AP + cg*16];
            #pragma unroll
            for (int j = 0; j < 16; j++)
                o[j] = fmaf(pv, vrow[j], o[j]);
        }
    }

    float inv = 1.f / l_i;
    #pragma unroll
    for (int j = 0; j < 16; j++)
        O[base + (size_t)(q0 + r) * Dq + cg*16 + j] = o[j] * inv;
}

// ---------------- host orchestration ----------------
extern "C" void kernel_launch(void* const* d_in, const int* in_sizes, int n_in,
                              void* d_out, int out_size)
{
    (void)n_in; (void)out_size;
    const float* x   = (const float*)d_in[0];
    const float* sn  = (const float*)d_in[1];
    const float* cs  = (const float*)d_in[2];
    const float* w1s[3] = {(const float*)d_in[3], (const float*)d_in[7],  (const float*)d_in[11]};
    const float* b1s[3] = {(const float*)d_in[4], (const float*)d_in[8],  (const float*)d_in[12]};
    const float* w2s[3] = {(const float*)d_in[5], (const float*)d_in[9],  (const float*)d_in[13]};
    const float* b2s[3] = {(const float*)d_in[6], (const float*)d_in[10], (const float*)d_in[14]};
    const float* ln1g = (const float*)d_in[15];
    const float* ln1b = (const float*)d_in[16];
    const float* ln2g = (const float*)d_in[17];
    const float* ln2b = (const float*)d_in[18];

    // Disambiguate metadata ordering by sizes:
    // signature order: wq,bq,wk,bk,wv,bv,wo,bo  -> in_sizes[20]==768
    // dict order:      wq,wk,wv,wo,bq,bk,bv,bo -> in_sizes[20]==589824
    const float *wq, *bqv, *wk, *bkv, *wv, *bvv, *wo, *bov;
    if (in_sizes[20] == 768) {
        wq = (const float*)d_in[19]; bqv = (const float*)d_in[20];
        wk = (const float*)d_in[21]; bkv = (const float*)d_in[22];
        wv = (const float*)d_in[23]; bvv = (const float*)d_in[24];
        wo = (const float*)d_in[25]; bov = (const float*)d_in[26];
    } else {
        wq = (const float*)d_in[19]; wk  = (const float*)d_in[20];
        wv = (const float*)d_in[21]; wo  = (const float*)d_in[22];
        bqv = (const float*)d_in[23]; bkv = (const float*)d_in[24];
        bvv = (const float*)d_in[25]; bov = (const float*)d_in[26];
    }
    const float* mw1 = (const float*)d_in[27]; const float* mb1 = (const float*)d_in[28];
    const float* mw2 = (const float*)d_in[29]; const float* mb2 = (const float*)d_in[30];

    float *t1, *pp, *ha, *hb, *gx, *gqk, *gq, *gk, *gv, *gatt, *go, *gx2;
    cudaGetSymbolAddress((void**)&t1,  g_t1);
    cudaGetSymbolAddress((void**)&pp,  g_p);
    cudaGetSymbolAddress((void**)&ha,  g_ha);
    cudaGetSymbolAddress((void**)&hb,  g_hb);
    cudaGetSymbolAddress((void**)&gx,  g_x);
    cudaGetSymbolAddress((void**)&gqk, g_qk);
    cudaGetSymbolAddress((void**)&gq,  g_q);
    cudaGetSymbolAddress((void**)&gk,  g_k);
    cudaGetSymbolAddress((void**)&gv,  g_v);
    cudaGetSymbolAddress((void**)&gatt,g_att);
    cudaGetSymbolAddress((void**)&go,  g_o);
    cudaGetSymbolAddress((void**)&gx2, g_x2);

    cudaMemcpyAsync(ha, x, sizeof(float)*(size_t)ROWS*Dq, cudaMemcpyDeviceToDevice);

    const int orderF[3] = {14, 384, 1024};
    const int Fs[3]     = {7, 128, 256};
    const int ords[3]   = {2, 3, 4};

    float* hc = ha; float* hn = hb;
    const int convBlocks = (ROWS * (Dq/4) + 255) / 256;

    for (int s3 = 0; s3 < 3; s3++) {
        sgemm128<1,0><<<dim3(24,32), 256>>>(hc, w1s[s3], b1s[s3], nullptr, t1, 3072, 768);
        sgemm128<0,0><<<dim3((orderF[s3]+127)/128, 32), 256>>>(t1, w2s[s3], b2s[s3], nullptr, pp, orderF[s3], 3072);
        for (int i = 0; i < ords[s3]; i++) {
            conv_gelu<<<convBlocks, 256>>>(hc, pp, hn, Fs[s3], orderF[s3], i * Fs[s3]);
            float* tmp = hc; hc = hn; hn = tmp;
        }
    }

    ln_kernel<<<ROWS, 256>>>(x, hc, ln1g, ln1b, gx);
    rope_kernel<<<(ROWS*384 + 255)/256, 256>>>(gx, sn, cs, gqk);

    sgemm128<0,0><<<dim3(6,32), 256>>>(gqk, wq, bqv, nullptr, gq, 768, 768);
    sgemm128<0,0><<<dim3(6,32), 256>>>(gqk, wk, bkv, nullptr, gk, 768, 768);
    sgemm128<0,0><<<dim3(6,32), 256>>>(gx,  wv, bvv, nullptr, gv, 768, 768);

    cudaFuncSetAttribute(attn_kernel, cudaFuncAttributeMaxDynamicSharedMemorySize, ATT_SMEM);
    attn_kernel<<<dim3(Lq/64, Bq*Hq), 256, ATT_SMEM>>>(gq, gk, gv, gatt);

    sgemm128<0,0><<<dim3(6,32), 256>>>(gatt, wo, bov, nullptr, go, 768, 768);
    ln_kernel<<<ROWS, 256>>>(gx, go, ln2g, ln2b, gx2);
    sgemm128<1,0><<<dim3(24,32), 256>>>(gx2, mw1, mb1, nullptr, t1, 3072, 768);
    sgemm128<0,1><<<dim3(6,32), 256>>>(t1, mw2, mb2, gx2, (float*)d_out, 768, 3072);
}

// round 5
// speedup vs baseline: 1.6126x; 1.6126x over previous
#include <cuda_runtime.h>
#include <math.h>
#include <stdint.h>

#define Bq 2
#define Lq 2048
#define Dq 768
#define Hq 12
#define ROWS (Bq*Lq)   /* 4096 */

// ---------------- scratch (device globals; no allocation allowed) ----------------
__device__ float g_t1[(size_t)ROWS*3072];
__device__ float g_p [(size_t)ROWS*1024];
__device__ float g_ha[(size_t)ROWS*Dq];
__device__ float g_hb[(size_t)ROWS*Dq];
__device__ float g_x [(size_t)ROWS*Dq];
__device__ float g_qk[(size_t)ROWS*Dq];
__device__ float g_q [(size_t)ROWS*Dq];
__device__ float g_k [(size_t)ROWS*Dq];
__device__ float g_v [(size_t)ROWS*Dq];
__device__ float g_att[(size_t)ROWS*Dq];
__device__ float g_o [(size_t)ROWS*Dq];
__device__ float g_x2[(size_t)ROWS*Dq];

__device__ __forceinline__ float gelu_f(float x){
    return 0.5f*x*(1.0f+erff(x*0.70710678118654752440f));
}

// TF32 rounding (matches cuBLAS input conversion for TF32 GEMMs)
__device__ __forceinline__ float tf32r(float x){
    uint32_t u;
    asm("cvt.rna.tf32.f32 %0, %1;" : "=r"(u) : "f"(x));
    return __uint_as_float(u);
}
__device__ __forceinline__ uint32_t tf32u(float x){
    uint32_t u;
    asm("cvt.rna.tf32.f32 %0, %1;" : "=r"(u) : "f"(x));
    return u;
}

// ---------------- tensor-core TF32 GEMM: C = A(MxK)@B(KxN) + bias [,GELU][,+Res]
// 128x128x32 block tile, 8 warps of 64x32, mma.sync.m16n8k8.tf32.
// M multiple of 128, K multiple of 32, N arbitrary even.
template<int GELU, int RES>
__global__ void __launch_bounds__(256) gemm_tc(
    const float* __restrict__ A, const float* __restrict__ Bm,
    const float* __restrict__ bias, const float* __restrict__ Rr,
    float* __restrict__ C, int N, int K)
{
    __shared__ uint32_t As[128*36];   // A[m][k], stride 36 (= 4 mod 32: frag banks 4g+c distinct)
    __shared__ uint32_t Bs[32*136];   // B[k][n], stride 136 (= 8 mod 32: frag banks 8c+g distinct)
    const int tid  = threadIdx.x;
    const int warp = tid >> 5, lane = tid & 31;
    const int g = lane >> 2, tc = lane & 3;
    const int wm0 = (warp & 1) * 64, wn0 = (warp >> 1) * 32;
    const int row0 = blockIdx.y * 128, col0 = blockIdx.x * 128;

    float acc[4][4][4] = {};

    const int ar = tid >> 3,  ac = (tid & 7) * 4;    // A loader: 32 rows/pass, 8 float4/row
    const int bk = tid >> 5,  bc = (tid & 31) * 4;   // B loader: 8 rows/pass, 32 float4/row
    const bool vecB = ((N & 3) == 0);

    for (int k0 = 0; k0 < K; k0 += 32) {
        #pragma unroll
        for (int p = 0; p < 4; p++) {
            int r = ar + p * 32;
            float4 v = *(const float4*)(A + (size_t)(row0 + r) * K + k0 + ac);
            uint32_t* dst = &As[r * 36 + ac];
            dst[0] = tf32u(v.x); dst[1] = tf32u(v.y);
            dst[2] = tf32u(v.z); dst[3] = tf32u(v.w);
        }
        #pragma unroll
        for (int p = 0; p < 4; p++) {
            int kr = bk + p * 8;
            uint32_t b4[4];
            if (vecB && (col0 + bc + 3 < N)) {
                float4 v = *(const float4*)(Bm + (size_t)(k0 + kr) * N + col0 + bc);
                b4[0] = tf32u(v.x); b4[1] = tf32u(v.y);
                b4[2] = tf32u(v.z); b4[3] = tf32u(v.w);
            } else {
                #pragma unroll
                for (int u = 0; u < 4; u++) {
                    int c = col0 + bc + u;
                    b4[u] = (c < N) ? tf32u(Bm[(size_t)(k0 + kr) * N + c]) : 0u;
                }
            }
            *(uint4*)&Bs[kr * 136 + bc] = *(uint4*)b4;
        }
        __syncthreads();

        #pragma unroll
        for (int k8 = 0; k8 < 32; k8 += 8) {
            uint32_t af[4][4], bf[4][2];
            #pragma unroll
            for (int mi = 0; mi < 4; mi++) {
                const uint32_t* base = &As[(wm0 + mi*16 + g) * 36 + k8 + tc];
                af[mi][0] = base[0];
                af[mi][1] = base[8*36];
                af[mi][2] = base[4];
                af[mi][3] = base[8*36 + 4];
            }
            #pragma unroll
            for (int ni = 0; ni < 4; ni++) {
                const uint32_t* base = &Bs[(k8 + tc) * 136 + wn0 + ni*8 + g];
                bf[ni][0] = base[0];
                bf[ni][1] = base[4*136];
            }
            #pragma unroll
            for (int mi = 0; mi < 4; mi++)
                #pragma unroll
                for (int ni = 0; ni < 4; ni++)
                    asm volatile(
                        "mma.sync.aligned.m16n8k8.row.col.f32.tf32.tf32.f32 "
                        "{%0,%1,%2,%3}, {%4,%5,%6,%7}, {%8,%9}, {%0,%1,%2,%3};"
                        : "+f"(acc[mi][ni][0]), "+f"(acc[mi][ni][1]),
                          "+f"(acc[mi][ni][2]), "+f"(acc[mi][ni][3])
                        : "r"(af[mi][0]), "r"(af[mi][1]), "r"(af[mi][2]), "r"(af[mi][3]),
                          "r"(bf[ni][0]), "r"(bf[ni][1]));
        }
        __syncthreads();
    }

    #pragma unroll
    for (int mi = 0; mi < 4; mi++) {
        int r0 = row0 + wm0 + mi*16 + g;
        #pragma unroll
        for (int ni = 0; ni < 4; ni++) {
            int c = col0 + wn0 + ni*8 + tc*2;
            if (c < N) {
                float b0 = bias[c], b1 = bias[c+1];
                float v0 = acc[mi][ni][0] + b0, v1 = acc[mi][ni][1] + b1;
                float v2 = acc[mi][ni][2] + b0, v3 = acc[mi][ni][3] + b1;
                if (GELU) { v0 = gelu_f(v0); v1 = gelu_f(v1); v2 = gelu_f(v2); v3 = gelu_f(v3); }
                if (RES) {
                    v0 += Rr[(size_t)r0*N + c];     v1 += Rr[(size_t)r0*N + c + 1];
                    v2 += Rr[(size_t)(r0+8)*N + c]; v3 += Rr[(size_t)(r0+8)*N + c + 1];
                }
                *(float2*)(C + (size_t)r0*N + c)     = make_float2(v0, v1);
                *(float2*)(C + (size_t)(r0+8)*N + c) = make_float2(v2, v3);
            }
        }
    }
}

// ---------------- data-dependent causal conv + GELU (fp32)
__global__ void conv_gelu(const float* __restrict__ h, const float* __restrict__ p,
                          float* __restrict__ out, int F, int pstride, int poff)
{
    int idx = blockIdx.x * blockDim.x + threadIdx.x;
    if (idx >= ROWS * (Dq/4)) return;
    int d4 = idx % (Dq/4);
    int bt = idx / (Dq/4);
    int t  = bt & (Lq - 1);
    const float* kr = p + (size_t)bt * pstride + poff;
    int mmax = min(F - 1, t);
    float ax = 0.f, ay = 0.f, az = 0.f, aw = 0.f;
    for (int m = mmax; m >= 0; --m) {
        float kv = __ldg(kr + m);
        const float4 hv = *(const float4*)(h + (size_t)(bt - m) * Dq + d4 * 4);
        ax = fmaf(kv, hv.x, ax);
        ay = fmaf(kv, hv.y, ay);
        az = fmaf(kv, hv.z, az);
        aw = fmaf(kv, hv.w, aw);
    }
    float4 o;
    o.x = gelu_f(ax); o.y = gelu_f(ay); o.z = gelu_f(az); o.w = gelu_f(aw);
    *(float4*)(out + (size_t)bt * Dq + d4 * 4) = o;
}

// ---------------- LayerNorm of (a+b): two-pass, fp64 accumulators
__global__ void ln_kernel(const float* __restrict__ a, const float* __restrict__ b,
                          const float* __restrict__ g, const float* __restrict__ be,
                          float* __restrict__ out)
{
    __shared__ double red[10];
    int row = blockIdx.x, tid = threadIdx.x;
    const float* pa = a + (size_t)row * Dq;
    const float* pb = b + (size_t)row * Dq;
    float v[3];
    double s = 0.0;
    #pragma unroll
    for (int i = 0; i < 3; i++) {
        float x = pa[tid + 256*i] + pb[tid + 256*i];
        v[i] = x; s += (double)x;
    }
    #pragma unroll
    for (int o = 16; o; o >>= 1) s += __shfl_down_sync(0xffffffffu, s, o);
    if ((tid & 31) == 0) red[tid >> 5] = s;
    __syncthreads();
    if (tid == 0) {
        double t = 0.0;
        #pragma unroll
        for (int w = 0; w < 8; w++) t += red[w];
        red[8] = t * (1.0/768.0);
    }
    __syncthreads();
    float mean = (float)red[8];

    double s2 = 0.0;
    #pragma unroll
    for (int i = 0; i < 3; i++) {
        double d = (double)v[i] - red[8];
        s2 += d * d;
    }
    #pragma unroll
    for (int o = 16; o; o >>= 1) s2 += __shfl_down_sync(0xffffffffu, s2, o);
    if ((tid & 31) == 0) red[tid >> 5] = s2;
    __syncthreads();
    if (tid == 0) {
        double t = 0.0;
        #pragma unroll
        for (int w = 0; w < 8; w++) t += red[w];
        red[9] = 1.0 / sqrt(t * (1.0/768.0) + 1e-5);
    }
    __syncthreads();
    float rs = (float)red[9];
    #pragma unroll
    for (int i = 0; i < 3; i++) {
        int c = tid + 256*i;
        out[(size_t)row * Dq + c] = (v[i] - mean) * rs * g[c] + be[c];
    }
}

// ---------------- RoPE
__global__ void rope_kernel(const float* __restrict__ x, const float* __restrict__ sn,
                            const float* __restrict__ cs, float* __restrict__ out)
{
    int idx = blockIdx.x * blockDim.x + threadIdx.x;
    if (idx >= ROWS * 384) return;
    int d = idx % 384, row = idx / 384, l = row & (Lq - 1);
    float x1 = x[(size_t)row * Dq + d];
    float x2 = x[(size_t)row * Dq + 384 + d];
    float sv = sn[l * 384 + d], cv = cs[l * 384 + d];
    out[(size_t)row * Dq + d]        = x1 * cv - x2 * sv;
    out[(size_t)row * Dq + 384 + d]  = x2 * cv + x1 * sv;
}

// ---------------- fused flash-style attention, hd=64, TF32-rounded, vectorized LDS
#define AS 68
#define ATT_SMEM (3*64*AS*4)
__global__ void __launch_bounds__(256) attn_kernel(
    const float* __restrict__ Q, const float* __restrict__ K,
    const float* __restrict__ V, float* __restrict__ O)
{
    extern __shared__ float sm[];
    float* Qs = sm;              // Q[r][d], stride AS
    float* KT = sm + 64*AS;      // K transposed [d][j]; reused as P[r][k]
    float* Vs = sm + 2*64*AS;    // V[k][d], stride AS
    int tid = threadIdx.x;
    int bh = blockIdx.y;
    int b = bh / Hq, h = bh % Hq;
    int q0 = blockIdx.x * 64;
    size_t base = (size_t)b * Lq * Dq + (size_t)h * 64;

    for (int i = tid; i < 64*16; i += 256) {
        int rr = i >> 4, c4 = (i & 15) * 4;
        float4 qv = *(const float4*)(Q + base + (size_t)(q0 + rr) * Dq + c4);
        float4 qr = make_float4(tf32r(qv.x), tf32r(qv.y), tf32r(qv.z), tf32r(qv.w));
        *(float4*)&Qs[rr*AS + c4] = qr;
    }

    int r = tid >> 2, cg = tid & 3;
    float m_i = -INFINITY, l_i = 0.f;
    float o[16];
    #pragma unroll
    for (int j = 0; j < 16; j++) o[j] = 0.f;

    for (int kt = 0; kt < Lq/64; ++kt) {
        __syncthreads();
        for (int i = tid; i < 64*16; i += 256) {
            int rr = i >> 4, c4 = (i & 15) * 4;
            float4 kv = *(const float4*)(K + base + (size_t)(kt*64 + rr) * Dq + c4);
            KT[(c4+0)*AS + rr] = tf32r(kv.x);
            KT[(c4+1)*AS + rr] = tf32r(kv.y);
            KT[(c4+2)*AS + rr] = tf32r(kv.z);
            KT[(c4+3)*AS + rr] = tf32r(kv.w);
            float4 vv = *(const float4*)(V + base + (size_t)(kt*64 + rr) * Dq + c4);
            float4 vr = make_float4(tf32r(vv.x), tf32r(vv.y), tf32r(vv.z), tf32r(vv.w));
            *(float4*)&Vs[rr*AS + c4] = vr;
        }
        __syncthreads();

        float s[16];
        #pragma unroll
        for (int j = 0; j < 16; j++) s[j] = 0.f;
        #pragma unroll 2
        for (int d = 0; d < 64; ++d) {
            float qd = Qs[r*AS + d];
            const float* krow = &KT[d*AS + cg*16];
            float4 k0 = *(const float4*)(krow);
            float4 k1 = *(const float4*)(krow + 4);
            float4 k2 = *(const float4*)(krow + 8);
            float4 k3 = *(const float4*)(krow + 12);
            s[0]  = fmaf(qd, k0.x, s[0]);  s[1]  = fmaf(qd, k0.y, s[1]);
            s[2]  = fmaf(qd, k0.z, s[2]);  s[3]  = fmaf(qd, k0.w, s[3]);
            s[4]  = fmaf(qd, k1.x, s[4]);  s[5]  = fmaf(qd, k1.y, s[5]);
            s[6]  = fmaf(qd, k1.z, s[6]);  s[7]  = fmaf(qd, k1.w, s[7]);
            s[8]  = fmaf(qd, k2.x, s[8]);  s[9]  = fmaf(qd, k2.y, s[9]);
            s[10] = fmaf(qd, k2.z, s[10]); s[11] = fmaf(qd, k2.w, s[11]);
            s[12] = fmaf(qd, k3.x, s[12]); s[13] = fmaf(qd, k3.y, s[13]);
            s[14] = fmaf(qd, k3.z, s[14]); s[15] = fmaf(qd, k3.w, s[15]);
        }
        #pragma unroll
        for (int j = 0; j < 16; j++) s[j] *= 0.125f;

        float mx = s[0];
        #pragma unroll
        for (int j = 1; j < 16; j++) mx = fmaxf(mx, s[j]);
        mx = fmaxf(mx, __shfl_xor_sync(0xffffffffu, mx, 1));
        mx = fmaxf(mx, __shfl_xor_sync(0xffffffffu, mx, 2));
        float m_new = fmaxf(m_i, mx);
        float ps = 0.f;
        #pragma unroll
        for (int j = 0; j < 16; j++) { s[j] = expf(s[j] - m_new); ps += s[j]; }
        ps += __shfl_xor_sync(0xffffffffu, ps, 1);
        ps += __shfl_xor_sync(0xffffffffu, ps, 2);
        float alpha = expf(m_i - m_new);
        l_i = l_i * alpha + ps;
        m_i = m_new;
        #pragma unroll
        for (int j = 0; j < 16; j++) o[j] *= alpha;

        __syncthreads();   // KT reads done -> reuse as P
        float* Pr = &KT[r*AS + cg*16];
        #pragma unroll
        for (int u = 0; u < 4; u++) {
            float4 pq = make_float4(tf32r(s[u*4+0]), tf32r(s[u*4+1]),
                                    tf32r(s[u*4+2]), tf32r(s[u*4+3]));
            *(float4*)(Pr + u*4) = pq;
        }
        __syncthreads();

        #pragma unroll 2
        for (int k = 0; k < 64; k++) {
            float pv = KT[r*AS + k];
            const float* vrow = &Vs[k*AS + cg*16];
            float4 v0 = *(const float4*)(vrow);
            float4 v1 = *(const float4*)(vrow + 4);
            float4 v2 = *(const float4*)(vrow + 8);
            float4 v3 = *(const float4*)(vrow + 12);
            o[0]  = fmaf(pv, v0.x, o[0]);  o[1]  = fmaf(pv, v0.y, o[1]);
            o[2]  = fmaf(pv, v0.z, o[2]);  o[3]  = fmaf(pv, v0.w, o[3]);
            o[4]  = fmaf(pv, v1.x, o[4]);  o[5]  = fmaf(pv, v1.y, o[5]);
            o[6]  = fmaf(pv, v1.z, o[6]);  o[7]  = fmaf(pv, v1.w, o[7]);
            o[8]  = fmaf(pv, v2.x, o[8]);  o[9]  = fmaf(pv, v2.y, o[9]);
            o[10] = fmaf(pv, v2.z, o[10]); o[11] = fmaf(pv, v2.w, o[11]);
            o[12] = fmaf(pv, v3.x, o[12]); o[13] = fmaf(pv, v3.y, o[13]);
            o[14] = fmaf(pv, v3.z, o[14]); o[15] = fmaf(pv, v3.w, o[15]);
        }
    }

    float inv = 1.f / l_i;
    #pragma unroll
    for (int j = 0; j < 16; j++)
        O[base + (size_t)(q0 + r) * Dq + cg*16 + j] = o[j] * inv;
}

// ---------------- host orchestration ----------------
extern "C" void kernel_launch(void* const* d_in, const int* in_sizes, int n_in,
                              void* d_out, int out_size)
{
    (void)n_in; (void)out_size;
    const float* x   = (const float*)d_in[0];
    const float* sn  = (const float*)d_in[1];
    const float* cs  = (const float*)d_in[2];
    const float* w1s[3] = {(const float*)d_in[3], (const float*)d_in[7],  (const float*)d_in[11]};
    const float* b1s[3] = {(const float*)d_in[4], (const float*)d_in[8],  (const float*)d_in[12]};
    const float* w2s[3] = {(const float*)d_in[5], (const float*)d_in[9],  (const float*)d_in[13]};
    const float* b2s[3] = {(const float*)d_in[6], (const float*)d_in[10], (const float*)d_in[14]};
    const float* ln1g = (const float*)d_in[15];
    const float* ln1b = (const float*)d_in[16];
    const float* ln2g = (const float*)d_in[17];
    const float* ln2b = (const float*)d_in[18];

    const float *wq, *bqv, *wk, *bkv, *wv, *bvv, *wo, *bov;
    if (in_sizes[20] == 768) {
        wq = (const float*)d_in[19]; bqv = (const float*)d_in[20];
        wk = (const float*)d_in[21]; bkv = (const float*)d_in[22];
        wv = (const float*)d_in[23]; bvv = (const float*)d_in[24];
        wo = (const float*)d_in[25]; bov = (const float*)d_in[26];
    } else {
        wq = (const float*)d_in[19]; wk  = (const float*)d_in[20];
        wv = (const float*)d_in[21]; wo  = (const float*)d_in[22];
        bqv = (const float*)d_in[23]; bkv = (const float*)d_in[24];
        bvv = (const float*)d_in[25]; bov = (const float*)d_in[26];
    }
    const float* mw1 = (const float*)d_in[27]; const float* mb1 = (const float*)d_in[28];
    const float* mw2 = (const float*)d_in[29]; const float* mb2 = (const float*)d_in[30];

    float *t1, *pp, *ha, *hb, *gx, *gqk, *gq, *gk, *gv, *gatt, *go, *gx2;
    cudaGetSymbolAddress((void**)&t1,  g_t1);
    cudaGetSymbolAddress((void**)&pp,  g_p);
    cudaGetSymbolAddress((void**)&ha,  g_ha);
    cudaGetSymbolAddress((void**)&hb,  g_hb);
    cudaGetSymbolAddress((void**)&gx,  g_x);
    cudaGetSymbolAddress((void**)&gqk, g_qk);
    cudaGetSymbolAddress((void**)&gq,  g_q);
    cudaGetSymbolAddress((void**)&gk,  g_k);
    cudaGetSymbolAddress((void**)&gv,  g_v);
    cudaGetSymbolAddress((void**)&gatt,g_att);
    cudaGetSymbolAddress((void**)&go,  g_o);
    cudaGetSymbolAddress((void**)&gx2, g_x2);

    cudaMemcpyAsync(ha, x, sizeof(float)*(size_t)ROWS*Dq, cudaMemcpyDeviceToDevice);

    const int orderF[3] = {14, 384, 1024};
    const int Fs[3]     = {7, 128, 256};
    const int ords[3]   = {2, 3, 4};

    float* hc = ha; float* hn = hb;
    const int convBlocks = (ROWS * (Dq/4) + 255) / 256;

    for (int s3 = 0; s3 < 3; s3++) {
        gemm_tc<1,0><<<dim3(24,32), 256>>>(hc, w1s[s3], b1s[s3], nullptr, t1, 3072, 768);
        gemm_tc<0,0><<<dim3((orderF[s3]+127)/128, 32), 256>>>(t1, w2s[s3], b2s[s3], nullptr, pp, orderF[s3], 3072);
        for (int i = 0; i < ords[s3]; i++) {
            conv_gelu<<<convBlocks, 256>>>(hc, pp, hn, Fs[s3], orderF[s3], i * Fs[s3]);
            float* tmp = hc; hc = hn; hn = tmp;
        }
    }

    ln_kernel<<<ROWS, 256>>>(x, hc, ln1g, ln1b, gx);
    rope_kernel<<<(ROWS*384 + 255)/256, 256>>>(gx, sn, cs, gqk);

    gemm_tc<0,0><<<dim3(6,32), 256>>>(gqk, wq, bqv, nullptr, gq, 768, 768);
    gemm_tc<0,0><<<dim3(6,32), 256>>>(gqk, wk, bkv, nullptr, gk, 768, 768);
    gemm_tc<0,0><<<dim3(6,32), 256>>>(gx,  wv, bvv, nullptr, gv, 768, 768);

    cudaFuncSetAttribute(attn_kernel, cudaFuncAttributeMaxDynamicSharedMemorySize, ATT_SMEM);
    attn_kernel<<<dim3(Lq/64, Bq*Hq), 256, ATT_SMEM>>>(gq, gk, gv, gatt);

    gemm_tc<0,0><<<dim3(6,32), 256>>>(gatt, wo, bov, nullptr, go, 768, 768);
    ln_kernel<<<ROWS, 256>>>(gx, go, ln2g, ln2b, gx2);
    gemm_tc<1,0><<<dim3(24,32), 256>>>(gx2, mw1, mb1, nullptr, t1, 3072, 768);
    gemm_tc<0,1><<<dim3(6,32), 256>>>(t1, mw2, mb2, gx2, (float*)d_out, 768, 3072);
}

// round 6
// speedup vs baseline: 1.8825x; 1.1674x over previous
#include <cuda_runtime.h>
#include <math.h>
#include <stdint.h>

#define Bq 2
#define Lq 2048
#define Dq 768
#define Hq 12
#define ROWS (Bq*Lq)   /* 4096 */

// ---------------- scratch (device globals; no allocation allowed) ----------------
__device__ float g_t1[(size_t)ROWS*3072];
__device__ float g_p [(size_t)ROWS*1024];
__device__ float g_ha[(size_t)ROWS*Dq];
__device__ float g_hb[(size_t)ROWS*Dq];
__device__ float g_x [(size_t)ROWS*Dq];
__device__ float g_qk[(size_t)ROWS*Dq];
__device__ float g_q [(size_t)ROWS*Dq];
__device__ float g_k [(size_t)ROWS*Dq];
__device__ float g_v [(size_t)ROWS*Dq];
__device__ float g_att[(size_t)ROWS*Dq];
__device__ float g_o [(size_t)ROWS*Dq];
__device__ float g_x2[(size_t)ROWS*Dq];

__device__ __forceinline__ float gelu_f(float x){
    return 0.5f*x*(1.0f+erff(x*0.70710678118654752440f));
}
__device__ __forceinline__ uint32_t tf32u(float x){
    uint32_t u;
    asm("cvt.rna.tf32.f32 %0, %1;" : "=r"(u) : "f"(x));
    return u;
}
__device__ __forceinline__ float tf32r(float x){
    return __uint_as_float(tf32u(x));
}
__device__ __forceinline__ void cp16(uint32_t smem_dst, const void* gsrc){
    asm volatile("cp.async.ca.shared.global [%0], [%1], 16;\n"
                 :: "r"(smem_dst), "l"(gsrc));
}

// ---------------- tensor-core TF32 GEMM body, 2-stage cp.async pipeline
// C = A(4096xK)@B(KxN) + bias [,GELU][,+Res]; K mult of 32.
// smem raw fp32; tf32 conversion at fragment load (numerics = cvt.rna everywhere).
#define GEMM_SMEM (2*(128*36 + 32*136)*4)
template<int GELU, int RES>
__device__ __forceinline__ void gemm_body(
    const float* __restrict__ A, const float* __restrict__ Bm,
    const float* __restrict__ bias, const float* __restrict__ Rr,
    float* __restrict__ C, int N, int K)
{
    extern __shared__ uint32_t smem_u[];
    uint32_t* AsB = smem_u;              // 2 x 128*36
    uint32_t* BsB = smem_u + 2*128*36;   // 2 x 32*136
    const int tid  = threadIdx.x;
    const int warp = tid >> 5, lane = tid & 31;
    const int g = lane >> 2, tc = lane & 3;
    const int wm0 = (warp & 1) * 64, wn0 = (warp >> 1) * 32;
    const int row0 = blockIdx.y * 128, col0 = blockIdx.x * 128;
    const bool colFull = (col0 + 128 <= N);

    float acc[4][4][4] = {};
    const int ar = tid >> 3,  ac = (tid & 7) * 4;
    const int bk = tid >> 5,  bc = (tid & 31) * 4;
    const int nt = K / 32;

    auto issue = [&](int kt, int s){
        uint32_t* as = AsB + s * (128*36);
        uint32_t* bs = BsB + s * (32*136);
        const int k0 = kt * 32;
        #pragma unroll
        for (int p = 0; p < 4; p++) {
            int r = ar + p * 32;
            cp16((uint32_t)__cvta_generic_to_shared(&as[r*36 + ac]),
                 A + (size_t)(row0 + r) * K + k0 + ac);
        }
        if (colFull) {
            #pragma unroll
            for (int p = 0; p < 4; p++) {
                int kr = bk + p * 8;
                cp16((uint32_t)__cvta_generic_to_shared(&bs[kr*136 + bc]),
                     Bm + (size_t)(k0 + kr) * N + col0 + bc);
            }
        } else {
            #pragma unroll
            for (int p = 0; p < 4; p++) {
                int kr = bk + p * 8;
                #pragma unroll
                for (int u = 0; u < 4; u++) {
                    int c = col0 + bc + u;
                    bs[kr*136 + bc + u] =
                        (c < N) ? __float_as_uint(Bm[(size_t)(k0 + kr) * N + c]) : 0u;
                }
            }
        }
        asm volatile("cp.async.commit_group;\n");
    };

    issue(0, 0);
    for (int kt = 0; kt < nt; kt++) {
        const int cur = kt & 1;
        if (kt + 1 < nt) {
            issue(kt + 1, cur ^ 1);
            asm volatile("cp.async.wait_group 1;\n");
        } else {
            asm volatile("cp.async.wait_group 0;\n");
        }
        __syncthreads();
        const uint32_t* as = AsB + cur * (128*36);
        const uint32_t* bs = BsB + cur * (32*136);
        #pragma unroll
        for (int k8 = 0; k8 < 32; k8 += 8) {
            uint32_t af[4][4], bf[4][2];
            #pragma unroll
            for (int mi = 0; mi < 4; mi++) {
                const uint32_t* base = &as[(wm0 + mi*16 + g) * 36 + k8 + tc];
                af[mi][0] = tf32u(__uint_as_float(base[0]));
                af[mi][1] = tf32u(__uint_as_float(base[8*36]));
                af[mi][2] = tf32u(__uint_as_float(base[4]));
                af[mi][3] = tf32u(__uint_as_float(base[8*36 + 4]));
            }
            #pragma unroll
            for (int ni = 0; ni < 4; ni++) {
                const uint32_t* base = &bs[(k8 + tc) * 136 + wn0 + ni*8 + g];
                bf[ni][0] = tf32u(__uint_as_float(base[0]));
                bf[ni][1] = tf32u(__uint_as_float(base[4*136]));
            }
            #pragma unroll
            for (int mi = 0; mi < 4; mi++)
                #pragma unroll
                for (int ni = 0; ni < 4; ni++)
                    asm volatile(
                        "mma.sync.aligned.m16n8k8.row.col.f32.tf32.tf32.f32 "
                        "{%0,%1,%2,%3}, {%4,%5,%6,%7}, {%8,%9}, {%0,%1,%2,%3};"
                        : "+f"(acc[mi][ni][0]), "+f"(acc[mi][ni][1]),
                          "+f"(acc[mi][ni][2]), "+f"(acc[mi][ni][3])
                        : "r"(af[mi][0]), "r"(af[mi][1]), "r"(af[mi][2]), "r"(af[mi][3]),
                          "r"(bf[ni][0]), "r"(bf[ni][1]));
        }
        __syncthreads();
    }

    #pragma unroll
    for (int mi = 0; mi < 4; mi++) {
        int r0 = row0 + wm0 + mi*16 + g;
        #pragma unroll
        for (int ni = 0; ni < 4; ni++) {
            int c = col0 + wn0 + ni*8 + tc*2;
            if (c < N) {
                float b0 = bias[c], b1 = bias[c+1];
                float v0 = acc[mi][ni][0] + b0, v1 = acc[mi][ni][1] + b1;
                float v2 = acc[mi][ni][2] + b0, v3 = acc[mi][ni][3] + b1;
                if (GELU) { v0 = gelu_f(v0); v1 = gelu_f(v1); v2 = gelu_f(v2); v3 = gelu_f(v3); }
                if (RES) {
                    v0 += Rr[(size_t)r0*N + c];     v1 += Rr[(size_t)r0*N + c + 1];
                    v2 += Rr[(size_t)(r0+8)*N + c]; v3 += Rr[(size_t)(r0+8)*N + c + 1];
                }
                *(float2*)(C + (size_t)r0*N + c)     = make_float2(v0, v1);
                *(float2*)(C + (size_t)(r0+8)*N + c) = make_float2(v2, v3);
            }
        }
    }
}

template<int GELU, int RES>
__global__ void __launch_bounds__(256, 2) gemm_tc(
    const float* __restrict__ A, const float* __restrict__ Bm,
    const float* __restrict__ bias, const float* __restrict__ Rr,
    float* __restrict__ C, int N, int K)
{
    gemm_body<GELU, RES>(A, Bm, bias, Rr, C, N, K);
}

// fused q/k/v projection: blockIdx.z selects {q,k,v}
__global__ void __launch_bounds__(256, 2) gemm_qkv(
    const float* __restrict__ gqk, const float* __restrict__ gx,
    const float* __restrict__ wq, const float* __restrict__ bq, float* __restrict__ oq,
    const float* __restrict__ wk, const float* __restrict__ bk, float* __restrict__ ok,
    const float* __restrict__ wv, const float* __restrict__ bv, float* __restrict__ ov)
{
    const int z = blockIdx.z;
    const float* A  = (z == 2) ? gx : gqk;
    const float* W  = (z == 0) ? wq : (z == 1) ? wk : wv;
    const float* bb = (z == 0) ? bq : (z == 1) ? bk : bv;
    float*       O  = (z == 0) ? oq : (z == 1) ? ok : ov;
    gemm_body<0,0>(A, W, bb, nullptr, O, 768, 768);
}

// ---------------- direct conv (F=7 only) + GELU, fp32, m descending
__global__ void conv_gelu(const float* __restrict__ h, const float* __restrict__ p,
                          float* __restrict__ out, int F, int pstride, int poff)
{
    int idx = blockIdx.x * blockDim.x + threadIdx.x;
    if (idx >= ROWS * (Dq/4)) return;
    int d4 = idx % (Dq/4);
    int bt = idx / (Dq/4);
    int t  = bt & (Lq - 1);
    const float* kr = p + (size_t)bt * pstride + poff;
    int mmax = min(F - 1, t);
    float ax = 0.f, ay = 0.f, az = 0.f, aw = 0.f;
    for (int m = mmax; m >= 0; --m) {
        float kv = __ldg(kr + m);
        const float4 hv = *(const float4*)(h + (size_t)(bt - m) * Dq + d4 * 4);
        ax = fmaf(kv, hv.x, ax);
        ay = fmaf(kv, hv.y, ay);
        az = fmaf(kv, hv.z, az);
        aw = fmaf(kv, hv.w, aw);
    }
    float4 o;
    o.x = gelu_f(ax); o.y = gelu_f(ay); o.z = gelu_f(az); o.w = gelu_f(aw);
    *(float4*)(out + (size_t)bt * Dq + d4 * 4) = o;
}

// ---------------- smem-tiled conv + GELU for F in {128, 256} (fp32 exact)
// block: 64 t x 64 d; thread = (tg 0..15 -> 4t, dg 0..15 -> 4d)
#define CONV_SMEM ((128*68 + 64*68)*4)
template<int F>
__global__ void __launch_bounds__(256) conv_tiled(
    const float* __restrict__ h, const float* __restrict__ p,
    float* __restrict__ out, int pstride, int poff)
{
    extern __shared__ float csm[];
    float* hs = csm;            // 128 x 68
    float* ps = csm + 128*68;   // 64 x 68
    const int tid = threadIdx.x;
    const int d0  = blockIdx.x * 64;
    const int bt0 = blockIdx.y * 64;
    const int batch = bt0 / Lq;
    const int t0    = bt0 & (Lq - 1);
    const int tg = tid >> 4;
    const int dg = tid & 15;

    float4 acc[4];
    #pragma unroll
    for (int i = 0; i < 4; i++) acc[i] = make_float4(0.f, 0.f, 0.f, 0.f);

    for (int m0 = F - 64; m0 >= 0; m0 -= 64) {
        for (int idx = tid; idx < 128*16; idx += 256) {
            int row = idx >> 4, c4 = (idx & 15) * 4;
            int lt = t0 - m0 - 64 + row;
            float4 v = make_float4(0.f, 0.f, 0.f, 0.f);
            if (lt >= 0)
                v = *(const float4*)(h + (size_t)(batch*Lq + lt) * Dq + d0 + c4);
            *(float4*)&hs[row*68 + c4] = v;
        }
        for (int idx = tid; idx < 64*16; idx += 256) {
            int row = idx >> 4, c4 = (idx & 15) * 4;
            float4 v = *(const float4*)(p + (size_t)(bt0 + row) * pstride + poff + m0 + c4);
            *(float4*)&ps[row*68 + c4] = v;
        }
        __syncthreads();
        #pragma unroll 4
        for (int mi = 63; mi >= 0; --mi) {
            #pragma unroll
            for (int i = 0; i < 4; i++) {
                float pk = ps[(tg*4 + i)*68 + mi];
                int rrow = tg*4 + i - mi + 64;
                float4 hv = *(const float4*)&hs[rrow*68 + dg*4];
                acc[i].x = fmaf(pk, hv.x, acc[i].x);
                acc[i].y = fmaf(pk, hv.y, acc[i].y);
                acc[i].z = fmaf(pk, hv.z, acc[i].z);
                acc[i].w = fmaf(pk, hv.w, acc[i].w);
            }
        }
        __syncthreads();
    }

    #pragma unroll
    for (int i = 0; i < 4; i++) {
        float4 o;
        o.x = gelu_f(acc[i].x); o.y = gelu_f(acc[i].y);
        o.z = gelu_f(acc[i].z); o.w = gelu_f(acc[i].w);
        *(float4*)(out + (size_t)(bt0 + tg*4 + i) * Dq + d0 + dg*4) = o;
    }
}

// ---------------- LayerNorm of (a+b): two-pass, fp64 accumulators
__global__ void ln_kernel(const float* __restrict__ a, const float* __restrict__ b,
                          const float* __restrict__ g, const float* __restrict__ be,
                          float* __restrict__ out)
{
    __shared__ double red[10];
    int row = blockIdx.x, tid = threadIdx.x;
    const float* pa = a + (size_t)row * Dq;
    const float* pb = b + (size_t)row * Dq;
    float v[3];
    double s = 0.0;
    #pragma unroll
    for (int i = 0; i < 3; i++) {
        float x = pa[tid + 256*i] + pb[tid + 256*i];
        v[i] = x; s += (double)x;
    }
    #pragma unroll
    for (int o = 16; o; o >>= 1) s += __shfl_down_sync(0xffffffffu, s, o);
    if ((tid & 31) == 0) red[tid >> 5] = s;
    __syncthreads();
    if (tid == 0) {
        double t = 0.0;
        #pragma unroll
        for (int w = 0; w < 8; w++) t += red[w];
        red[8] = t * (1.0/768.0);
    }
    __syncthreads();
    float mean = (float)red[8];

    double s2 = 0.0;
    #pragma unroll
    for (int i = 0; i < 3; i++) {
        double d = (double)v[i] - red[8];
        s2 += d * d;
    }
    #pragma unroll
    for (int o = 16; o; o >>= 1) s2 += __shfl_down_sync(0xffffffffu, s2, o);
    if ((tid & 31) == 0) red[tid >> 5] = s2;
    __syncthreads();
    if (tid == 0) {
        double t = 0.0;
        #pragma unroll
        for (int w = 0; w < 8; w++) t += red[w];
        red[9] = 1.0 / sqrt(t * (1.0/768.0) + 1e-5);
    }
    __syncthreads();
    float rs = (float)red[9];
    #pragma unroll
    for (int i = 0; i < 3; i++) {
        int c = tid + 256*i;
        out[(size_t)row * Dq + c] = (v[i] - mean) * rs * g[c] + be[c];
    }
}

// ---------------- RoPE
__global__ void rope_kernel(const float* __restrict__ x, const float* __restrict__ sn,
                            const float* __restrict__ cs, float* __restrict__ out)
{
    int idx = blockIdx.x * blockDim.x + threadIdx.x;
    if (idx >= ROWS * 384) return;
    int d = idx % 384, row = idx / 384, l = row & (Lq - 1);
    float x1 = x[(size_t)row * Dq + d];
    float x2 = x[(size_t)row * Dq + 384 + d];
    float sv = sn[l * 384 + d], cv = cs[l * 384 + d];
    out[(size_t)row * Dq + d]        = x1 * cv - x2 * sv;
    out[(size_t)row * Dq + 384 + d]  = x2 * cv + x1 * sv;
}

// ---------------- fused flash-style attention, hd=64, TF32-rounded, vectorized LDS
#define AS 68
#define ATT_SMEM (3*64*AS*4)
__global__ void __launch_bounds__(256) attn_kernel(
    const float* __restrict__ Q, const float* __restrict__ K,
    const float* __restrict__ V, float* __restrict__ O)
{
    extern __shared__ float sm[];
    float* Qs = sm;
    float* KT = sm + 64*AS;
    float* Vs = sm + 2*64*AS;
    int tid = threadIdx.x;
    int bh = blockIdx.y;
    int b = bh / Hq, h = bh % Hq;
    int q0 = blockIdx.x * 64;
    size_t base = (size_t)b * Lq * Dq + (size_t)h * 64;

    for (int i = tid; i < 64*16; i += 256) {
        int rr = i >> 4, c4 = (i & 15) * 4;
        float4 qv = *(const float4*)(Q + base + (size_t)(q0 + rr) * Dq + c4);
        float4 qr = make_float4(tf32r(qv.x), tf32r(qv.y), tf32r(qv.z), tf32r(qv.w));
        *(float4*)&Qs[rr*AS + c4] = qr;
    }

    int r = tid >> 2, cg = tid & 3;
    float m_i = -INFINITY, l_i = 0.f;
    float o[16];
    #pragma unroll
    for (int j = 0; j < 16; j++) o[j] = 0.f;

    for (int kt = 0; kt < Lq/64; ++kt) {
        __syncthreads();
        for (int i = tid; i < 64*16; i += 256) {
            int rr = i >> 4, c4 = (i & 15) * 4;
            float4 kv = *(const float4*)(K + base + (size_t)(kt*64 + rr) * Dq + c4);
            KT[(c4+0)*AS + rr] = tf32r(kv.x);
            KT[(c4+1)*AS + rr] = tf32r(kv.y);
            KT[(c4+2)*AS + rr] = tf32r(kv.z);
            KT[(c4+3)*AS + rr] = tf32r(kv.w);
            float4 vv = *(const float4*)(V + base + (size_t)(kt*64 + rr) * Dq + c4);
            float4 vr = make_float4(tf32r(vv.x), tf32r(vv.y), tf32r(vv.z), tf32r(vv.w));
            *(float4*)&Vs[rr*AS + c4] = vr;
        }
        __syncthreads();

        float s[16];
        #pragma unroll
        for (int j = 0; j < 16; j++) s[j] = 0.f;
        #pragma unroll 2
        for (int d = 0; d < 64; ++d) {
            float qd = Qs[r*AS + d];
            const float* krow = &KT[d*AS + cg*16];
            float4 k0 = *(const float4*)(krow);
            float4 k1 = *(const float4*)(krow + 4);
            float4 k2 = *(const float4*)(krow + 8);
            float4 k3 = *(const float4*)(krow + 12);
            s[0]  = fmaf(qd, k0.x, s[0]);  s[1]  = fmaf(qd, k0.y, s[1]);
            s[2]  = fmaf(qd, k0.z, s[2]);  s[3]  = fmaf(qd, k0.w, s[3]);
            s[4]  = fmaf(qd, k1.x, s[4]);  s[5]  = fmaf(qd, k1.y, s[5]);
            s[6]  = fmaf(qd, k1.z, s[6]);  s[7]  = fmaf(qd, k1.w, s[7]);
            s[8]  = fmaf(qd, k2.x, s[8]);  s[9]  = fmaf(qd, k2.y, s[9]);
            s[10] = fmaf(qd, k2.z, s[10]); s[11] = fmaf(qd, k2.w, s[11]);
            s[12] = fmaf(qd, k3.x, s[12]); s[13] = fmaf(qd, k3.y, s[13]);
            s[14] = fmaf(qd, k3.z, s[14]); s[15] = fmaf(qd, k3.w, s[15]);
        }
        #pragma unroll
        for (int j = 0; j < 16; j++) s[j] *= 0.125f;

        float mx = s[0];
        #pragma unroll
        for (int j = 1; j < 16; j++) mx = fmaxf(mx, s[j]);
        mx = fmaxf(mx, __shfl_xor_sync(0xffffffffu, mx, 1));
        mx = fmaxf(mx, __shfl_xor_sync(0xffffffffu, mx, 2));
        float m_new = fmaxf(m_i, mx);
        float ps = 0.f;
        #pragma unroll
        for (int j = 0; j < 16; j++) { s[j] = expf(s[j] - m_new); ps += s[j]; }
        ps += __shfl_xor_sync(0xffffffffu, ps, 1);
        ps += __shfl_xor_sync(0xffffffffu, ps, 2);
        float alpha = expf(m_i - m_new);
        l_i = l_i * alpha + ps;
        m_i = m_new;
        #pragma unroll
        for (int j = 0; j < 16; j++) o[j] *= alpha;

        __syncthreads();
        float* Pr = &KT[r*AS + cg*16];
        #pragma unroll
        for (int u = 0; u < 4; u++) {
            float4 pq = make_float4(tf32r(s[u*4+0]), tf32r(s[u*4+1]),
                                    tf32r(s[u*4+2]), tf32r(s[u*4+3]));
            *(float4*)(Pr + u*4) = pq;
        }
        __syncthreads();

        #pragma unroll 2
        for (int k = 0; k < 64; k++) {
            float pv = KT[r*AS + k];
            const float* vrow = &Vs[k*AS + cg*16];
            float4 v0 = *(const float4*)(vrow);
            float4 v1 = *(const float4*)(vrow + 4);
            float4 v2 = *(const float4*)(vrow + 8);
            float4 v3 = *(const float4*)(vrow + 12);
            o[0]  = fmaf(pv, v0.x, o[0]);  o[1]  = fmaf(pv, v0.y, o[1]);
            o[2]  = fmaf(pv, v0.z, o[2]);  o[3]  = fmaf(pv, v0.w, o[3]);
            o[4]  = fmaf(pv, v1.x, o[4]);  o[5]  = fmaf(pv, v1.y, o[5]);
            o[6]  = fmaf(pv, v1.z, o[6]);  o[7]  = fmaf(pv, v1.w, o[7]);
            o[8]  = fmaf(pv, v2.x, o[8]);  o[9]  = fmaf(pv, v2.y, o[9]);
            o[10] = fmaf(pv, v2.z, o[10]); o[11] = fmaf(pv, v2.w, o[11]);
            o[12] = fmaf(pv, v3.x, o[12]); o[13] = fmaf(pv, v3.y, o[13]);
            o[14] = fmaf(pv, v3.z, o[14]); o[15] = fmaf(pv, v3.w, o[15]);
        }
    }

    float inv = 1.f / l_i;
    #pragma unroll
    for (int j = 0; j < 16; j++)
        O[base + (size_t)(q0 + r) * Dq + cg*16 + j] = o[j] * inv;
}

// ---------------- host orchestration ----------------
extern "C" void kernel_launch(void* const* d_in, const int* in_sizes, int n_in,
                              void* d_out, int out_size)
{
    (void)n_in; (void)out_size;
    const float* x   = (const float*)d_in[0];
    const float* sn  = (const float*)d_in[1];
    const float* cs  = (const float*)d_in[2];
    const float* w1s[3] = {(const float*)d_in[3], (const float*)d_in[7],  (const float*)d_in[11]};
    const float* b1s[3] = {(const float*)d_in[4], (const float*)d_in[8],  (const float*)d_in[12]};
    const float* w2s[3] = {(const float*)d_in[5], (const float*)d_in[9],  (const float*)d_in[13]};
    const float* b2s[3] = {(const float*)d_in[6], (const float*)d_in[10], (const float*)d_in[14]};
    const float* ln1g = (const float*)d_in[15];
    const float* ln1b = (const float*)d_in[16];
    const float* ln2g = (const float*)d_in[17];
    const float* ln2b = (const float*)d_in[18];

    const float *wq, *bqv, *wk, *bkv, *wv, *bvv, *wo, *bov;
    if (in_sizes[20] == 768) {
        wq = (const float*)d_in[19]; bqv = (const float*)d_in[20];
        wk = (const float*)d_in[21]; bkv = (const float*)d_in[22];
        wv = (const float*)d_in[23]; bvv = (const float*)d_in[24];
        wo = (const float*)d_in[25]; bov = (const float*)d_in[26];
    } else {
        wq = (const float*)d_in[19]; wk  = (const float*)d_in[20];
        wv = (const float*)d_in[21]; wo  = (const float*)d_in[22];
        bqv = (const float*)d_in[23]; bkv = (const float*)d_in[24];
        bvv = (const float*)d_in[25]; bov = (const float*)d_in[26];
    }
    const float* mw1 = (const float*)d_in[27]; const float* mb1 = (const float*)d_in[28];
    const float* mw2 = (const float*)d_in[29]; const float* mb2 = (const float*)d_in[30];

    float *t1, *pp, *ha, *hb, *gx, *gqk, *gq, *gk, *gv, *gatt, *go, *gx2;
    cudaGetSymbolAddress((void**)&t1,  g_t1);
    cudaGetSymbolAddress((void**)&pp,  g_p);
    cudaGetSymbolAddress((void**)&ha,  g_ha);
    cudaGetSymbolAddress((void**)&hb,  g_hb);
    cudaGetSymbolAddress((void**)&gx,  g_x);
    cudaGetSymbolAddress((void**)&gqk, g_qk);
    cudaGetSymbolAddress((void**)&gq,  g_q);
    cudaGetSymbolAddress((void**)&gk,  g_k);
    cudaGetSymbolAddress((void**)&gv,  g_v);
    cudaGetSymbolAddress((void**)&gatt,g_att);
    cudaGetSymbolAddress((void**)&go,  g_o);
    cudaGetSymbolAddress((void**)&gx2, g_x2);

    // enable >48KB dynamic smem (host-side attribute set; idempotent)
    cudaFuncSetAttribute(gemm_tc<1,0>, cudaFuncAttributeMaxDynamicSharedMemorySize, GEMM_SMEM);
    cudaFuncSetAttribute(gemm_tc<0,0>, cudaFuncAttributeMaxDynamicSharedMemorySize, GEMM_SMEM);
    cudaFuncSetAttribute(gemm_tc<0,1>, cudaFuncAttributeMaxDynamicSharedMemorySize, GEMM_SMEM);
    cudaFuncSetAttribute(gemm_qkv,     cudaFuncAttributeMaxDynamicSharedMemorySize, GEMM_SMEM);
    cudaFuncSetAttribute(conv_tiled<128>, cudaFuncAttributeMaxDynamicSharedMemorySize, CONV_SMEM);
    cudaFuncSetAttribute(conv_tiled<256>, cudaFuncAttributeMaxDynamicSharedMemorySize, CONV_SMEM);
    cudaFuncSetAttribute(attn_kernel,  cudaFuncAttributeMaxDynamicSharedMemorySize, ATT_SMEM);

    cudaMemcpyAsync(ha, x, sizeof(float)*(size_t)ROWS*Dq, cudaMemcpyDeviceToDevice);

    const int orderF[3] = {14, 384, 1024};
    const int Fs[3]     = {7, 128, 256};
    const int ords[3]   = {2, 3, 4};

    float* hc = ha; float* hn = hb;
    const int convBlocks = (ROWS * (Dq/4) + 255) / 256;

    for (int s3 = 0; s3 < 3; s3++) {
        gemm_tc<1,0><<<dim3(24,32), 256, GEMM_SMEM>>>(hc, w1s[s3], b1s[s3], nullptr, t1, 3072, 768);
        gemm_tc<0,0><<<dim3((orderF[s3]+127)/128, 32), 256, GEMM_SMEM>>>(t1, w2s[s3], b2s[s3], nullptr, pp, orderF[s3], 3072);
        for (int i = 0; i < ords[s3]; i++) {
            if (Fs[s3] == 7)
                conv_gelu<<<convBlocks, 256>>>(hc, pp, hn, 7, orderF[s3], i * 7);
            else if (Fs[s3] == 128)
                conv_tiled<128><<<dim3(12,64), 256, CONV_SMEM>>>(hc, pp, hn, orderF[s3], i * 128);
            else
                conv_tiled<256><<<dim3(12,64), 256, CONV_SMEM>>>(hc, pp, hn, orderF[s3], i * 256);
            float* tmp = hc; hc = hn; hn = tmp;
        }
    }

    ln_kernel<<<ROWS, 256>>>(x, hc, ln1g, ln1b, gx);
    rope_kernel<<<(ROWS*384 + 255)/256, 256>>>(gx, sn, cs, gqk);

    gemm_qkv<<<dim3(6,32,3), 256, GEMM_SMEM>>>(gqk, gx, wq, bqv, gq, wk, bkv, gk, wv, bvv, gv);

    attn_kernel<<<dim3(Lq/64, Bq*Hq), 256, ATT_SMEM>>>(gq, gk, gv, gatt);

    gemm_tc<0,0><<<dim3(6,32), 256, GEMM_SMEM>>>(gatt, wo, bov, nullptr, go, 768, 768);
    ln_kernel<<<ROWS, 256>>>(gx, go, ln2g, ln2b, gx2);
    gemm_tc<1,0><<<dim3(24,32), 256, GEMM_SMEM>>>(gx2, mw1, mb1, nullptr, t1, 3072, 768);
    gemm_tc<0,1><<<dim3(6,32), 256, GEMM_SMEM>>>(t1, mw2, mb2, gx2, (float*)d_out, 768, 3072);
}

// round 7
// speedup vs baseline: 4.6252x; 2.4569x over previous
#include <cuda_runtime.h>
#include <math.h>
#include <stdint.h>

#define Bq 2
#define Lq 2048
#define Dq 768
#define Hq 12
#define ROWS (Bq*Lq)   /* 4096 */

// ---------------- scratch (device globals; no allocation allowed) ----------------
__device__ float g_t1[(size_t)ROWS*3072];
__device__ float g_p [(size_t)ROWS*1024];
__device__ float g_ha[(size_t)ROWS*Dq];
__device__ float g_hb[(size_t)ROWS*Dq];
__device__ float g_x [(size_t)ROWS*Dq];
__device__ float g_qk[(size_t)ROWS*Dq];
__device__ float g_q [(size_t)ROWS*Dq];
__device__ float g_k [(size_t)ROWS*Dq];
__device__ float g_v [(size_t)ROWS*Dq];
__device__ float g_att[(size_t)ROWS*Dq];
__device__ float g_o [(size_t)ROWS*Dq];
__device__ float g_x2[(size_t)ROWS*Dq];
__device__ float g_wr[18524160];   // pre-rounded weights (74MB)

__device__ __forceinline__ float gelu_f(float x){
    return 0.5f*x*(1.0f+erff(x*0.70710678118654752440f));
}
__device__ __forceinline__ uint32_t tf32u(float x){
    uint32_t u;
    asm("cvt.rna.tf32.f32 %0, %1;" : "=r"(u) : "f"(x));
    return u;
}
__device__ __forceinline__ float tf32r(float x){
    return __uint_as_float(tf32u(x));
}
__device__ __forceinline__ void cp16(uint32_t smem_dst, const void* gsrc){
    asm volatile("cp.async.ca.shared.global [%0], [%1], 16;\n"
                 :: "r"(smem_dst), "l"(gsrc));
}

// ---------------- tf32 round-copy (weights pre-rounding) ----------------
__global__ void round_copy(const float4* __restrict__ in, float4* __restrict__ out, int n4)
{
    int i = blockIdx.x * blockDim.x + threadIdx.x;
    if (i < n4) {
        float4 v = in[i];
        out[i] = make_float4(tf32r(v.x), tf32r(v.y), tf32r(v.z), tf32r(v.w));
    }
}

// ---------------- tensor-core TF32 GEMM body, 2-stage cp.async pipeline
// C = A(4096xK)@B(KxN) + bias [,GELU][,+Res][,tf32-round-out]; K mult of 32.
// B must be pre-rounded to tf32. A rounded at frag load iff CVTA.
#define GEMM_SMEM (2*(128*36 + 32*136)*4)
template<int GELU, int RES, int CVTA, int ROUT>
__device__ __forceinline__ void gemm_body(
    const float* __restrict__ A, const float* __restrict__ Bm,
    const float* __restrict__ bias, const float* __restrict__ Rr,
    float* __restrict__ C, int N, int K)
{
    extern __shared__ uint32_t smem_u[];
    uint32_t* AsB = smem_u;              // 2 x 128*36
    uint32_t* BsB = smem_u + 2*128*36;   // 2 x 32*136
    const int tid  = threadIdx.x;
    const int warp = tid >> 5, lane = tid & 31;
    const int g = lane >> 2, tc = lane & 3;
    const int wm0 = (warp & 1) * 64, wn0 = (warp >> 1) * 32;
    const int row0 = blockIdx.y * 128, col0 = blockIdx.x * 128;
    const bool colFull = (col0 + 128 <= N);

    float acc[4][4][4] = {};
    const int ar = tid >> 3,  ac = (tid & 7) * 4;
    const int bk = tid >> 5,  bc = (tid & 31) * 4;
    const int nt = K / 32;

    auto issue = [&](int kt, int s){
        uint32_t* as = AsB + s * (128*36);
        uint32_t* bs = BsB + s * (32*136);
        const int k0 = kt * 32;
        #pragma unroll
        for (int p = 0; p < 4; p++) {
            int r = ar + p * 32;
            cp16((uint32_t)__cvta_generic_to_shared(&as[r*36 + ac]),
                 A + (size_t)(row0 + r) * K + k0 + ac);
        }
        if (colFull) {
            #pragma unroll
            for (int p = 0; p < 4; p++) {
                int kr = bk + p * 8;
                cp16((uint32_t)__cvta_generic_to_shared(&bs[kr*136 + bc]),
                     Bm + (size_t)(k0 + kr) * N + col0 + bc);
            }
        } else {
            #pragma unroll
            for (int p = 0; p < 4; p++) {
                int kr = bk + p * 8;
                #pragma unroll
                for (int u = 0; u < 4; u++) {
                    int c = col0 + bc + u;
                    bs[kr*136 + bc + u] =
                        (c < N) ? __float_as_uint(Bm[(size_t)(k0 + kr) * N + c]) : 0u;
                }
            }
        }
        asm volatile("cp.async.commit_group;\n");
    };

    issue(0, 0);
    for (int kt = 0; kt < nt; kt++) {
        const int cur = kt & 1;
        if (kt + 1 < nt) {
            issue(kt + 1, cur ^ 1);
            asm volatile("cp.async.wait_group 1;\n");
        } else {
            asm volatile("cp.async.wait_group 0;\n");
        }
        __syncthreads();
        const uint32_t* as = AsB + cur * (128*36);
        const uint32_t* bs = BsB + cur * (32*136);
        #pragma unroll
        for (int k8 = 0; k8 < 32; k8 += 8) {
            uint32_t af[4][4], bf[4][2];
            #pragma unroll
            for (int mi = 0; mi < 4; mi++) {
                const uint32_t* base = &as[(wm0 + mi*16 + g) * 36 + k8 + tc];
                if (CVTA) {
                    af[mi][0] = tf32u(__uint_as_float(base[0]));
                    af[mi][1] = tf32u(__uint_as_float(base[8*36]));
                    af[mi][2] = tf32u(__uint_as_float(base[4]));
                    af[mi][3] = tf32u(__uint_as_float(base[8*36 + 4]));
                } else {
                    af[mi][0] = base[0];
                    af[mi][1] = base[8*36];
                    af[mi][2] = base[4];
                    af[mi][3] = base[8*36 + 4];
                }
            }
            #pragma unroll
            for (int ni = 0; ni < 4; ni++) {
                const uint32_t* base = &bs[(k8 + tc) * 136 + wn0 + ni*8 + g];
                bf[ni][0] = base[0];
                bf[ni][1] = base[4*136];
            }
            #pragma unroll
            for (int mi = 0; mi < 4; mi++)
                #pragma unroll
                for (int ni = 0; ni < 4; ni++)
                    asm volatile(
                        "mma.sync.aligned.m16n8k8.row.col.f32.tf32.tf32.f32 "
                        "{%0,%1,%2,%3}, {%4,%5,%6,%7}, {%8,%9}, {%0,%1,%2,%3};"
                        : "+f"(acc[mi][ni][0]), "+f"(acc[mi][ni][1]),
                          "+f"(acc[mi][ni][2]), "+f"(acc[mi][ni][3])
                        : "r"(af[mi][0]), "r"(af[mi][1]), "r"(af[mi][2]), "r"(af[mi][3]),
                          "r"(bf[ni][0]), "r"(bf[ni][1]));
        }
        __syncthreads();
    }

    #pragma unroll
    for (int mi = 0; mi < 4; mi++) {
        int r0 = row0 + wm0 + mi*16 + g;
        #pragma unroll
        for (int ni = 0; ni < 4; ni++) {
            int c = col0 + wn0 + ni*8 + tc*2;
            if (c < N) {
                float b0 = bias[c], b1 = bias[c+1];
                float v0 = acc[mi][ni][0] + b0, v1 = acc[mi][ni][1] + b1;
                float v2 = acc[mi][ni][2] + b0, v3 = acc[mi][ni][3] + b1;
                if (GELU) { v0 = gelu_f(v0); v1 = gelu_f(v1); v2 = gelu_f(v2); v3 = gelu_f(v3); }
                if (ROUT) { v0 = tf32r(v0); v1 = tf32r(v1); v2 = tf32r(v2); v3 = tf32r(v3); }
                if (RES) {
                    v0 += Rr[(size_t)r0*N + c];     v1 += Rr[(size_t)r0*N + c + 1];
                    v2 += Rr[(size_t)(r0+8)*N + c]; v3 += Rr[(size_t)(r0+8)*N + c + 1];
                }
                *(float2*)(C + (size_t)r0*N + c)     = make_float2(v0, v1);
                *(float2*)(C + (size_t)(r0+8)*N + c) = make_float2(v2, v3);
            }
        }
    }
}

template<int GELU, int RES, int CVTA, int ROUT>
__global__ void __launch_bounds__(256, 2) gemm_tc(
    const float* __restrict__ A, const float* __restrict__ Bm,
    const float* __restrict__ bias, const float* __restrict__ Rr,
    float* __restrict__ C, int N, int K)
{
    gemm_body<GELU, RES, CVTA, ROUT>(A, Bm, bias, Rr, C, N, K);
}

// fused q/k/v projection: blockIdx.z selects {q,k,v}; outputs tf32-rounded
__global__ void __launch_bounds__(256, 2) gemm_qkv(
    const float* __restrict__ gqk, const float* __restrict__ gx,
    const float* __restrict__ wq, const float* __restrict__ bq, float* __restrict__ oq,
    const float* __restrict__ wk, const float* __restrict__ bk, float* __restrict__ ok,
    const float* __restrict__ wv, const float* __restrict__ bv, float* __restrict__ ov)
{
    const int z = blockIdx.z;
    if (z == 2) {
        gemm_body<0,0,1,1>(gx, wv, bv, nullptr, ov, 768, 768);   // gx is raw fp32
    } else if (z == 1) {
        gemm_body<0,0,0,1>(gqk, wk, bk, nullptr, ok, 768, 768);  // gqk pre-rounded
    } else {
        gemm_body<0,0,0,1>(gqk, wq, bq, nullptr, oq, 768, 768);
    }
}

// ---------------- direct conv (F=7 only) + GELU, fp32, m descending
__global__ void conv_gelu(const float* __restrict__ h, const float* __restrict__ p,
                          float* __restrict__ out, int F, int pstride, int poff)
{
    int idx = blockIdx.x * blockDim.x + threadIdx.x;
    if (idx >= ROWS * (Dq/4)) return;
    int d4 = idx % (Dq/4);
    int bt = idx / (Dq/4);
    int t  = bt & (Lq - 1);
    const float* kr = p + (size_t)bt * pstride + poff;
    int mmax = min(F - 1, t);
    float ax = 0.f, ay = 0.f, az = 0.f, aw = 0.f;
    for (int m = mmax; m >= 0; --m) {
        float kv = __ldg(kr + m);
        const float4 hv = *(const float4*)(h + (size_t)(bt - m) * Dq + d4 * 4);
        ax = fmaf(kv, hv.x, ax);
        ay = fmaf(kv, hv.y, ay);
        az = fmaf(kv, hv.z, az);
        aw = fmaf(kv, hv.w, aw);
    }
    float4 o;
    o.x = gelu_f(ax); o.y = gelu_f(ay); o.z = gelu_f(az); o.w = gelu_f(aw);
    *(float4*)(out + (size_t)bt * Dq + d4 * 4) = o;
}

// ---------------- smem-tiled conv + GELU for F in {128, 256} (fp32 exact)
#define CONV_SMEM ((128*68 + 64*68)*4)
template<int F>
__global__ void __launch_bounds__(256) conv_tiled(
    const float* __restrict__ h, const float* __restrict__ p,
    float* __restrict__ out, int pstride, int poff)
{
    extern __shared__ float csm[];
    float* hs = csm;            // 128 x 68
    float* ps = csm + 128*68;   // 64 x 68
    const int tid = threadIdx.x;
    const int d0  = blockIdx.x * 64;
    const int bt0 = blockIdx.y * 64;
    const int batch = bt0 / Lq;
    const int t0    = bt0 & (Lq - 1);
    const int tg = tid >> 4;
    const int dg = tid & 15;

    float4 acc[4];
    #pragma unroll
    for (int i = 0; i < 4; i++) acc[i] = make_float4(0.f, 0.f, 0.f, 0.f);

    for (int m0 = F - 64; m0 >= 0; m0 -= 64) {
        for (int idx = tid; idx < 128*16; idx += 256) {
            int row = idx >> 4, c4 = (idx & 15) * 4;
            int lt = t0 - m0 - 64 + row;
            float4 v = make_float4(0.f, 0.f, 0.f, 0.f);
            if (lt >= 0)
                v = *(const float4*)(h + (size_t)(batch*Lq + lt) * Dq + d0 + c4);
            *(float4*)&hs[row*68 + c4] = v;
        }
        for (int idx = tid; idx < 64*16; idx += 256) {
            int row = idx >> 4, c4 = (idx & 15) * 4;
            float4 v = *(const float4*)(p + (size_t)(bt0 + row) * pstride + poff + m0 + c4);
            *(float4*)&ps[row*68 + c4] = v;
        }
        __syncthreads();
        #pragma unroll 4
        for (int mi = 63; mi >= 0; --mi) {
            #pragma unroll
            for (int i = 0; i < 4; i++) {
                float pk = ps[(tg*4 + i)*68 + mi];
                int rrow = tg*4 + i - mi + 64;
                float4 hv = *(const float4*)&hs[rrow*68 + dg*4];
                acc[i].x = fmaf(pk, hv.x, acc[i].x);
                acc[i].y = fmaf(pk, hv.y, acc[i].y);
                acc[i].z = fmaf(pk, hv.z, acc[i].z);
                acc[i].w = fmaf(pk, hv.w, acc[i].w);
            }
        }
        __syncthreads();
    }

    #pragma unroll
    for (int i = 0; i < 4; i++) {
        float4 o;
        o.x = gelu_f(acc[i].x); o.y = gelu_f(acc[i].y);
        o.z = gelu_f(acc[i].z); o.w = gelu_f(acc[i].w);
        *(float4*)(out + (size_t)(bt0 + tg*4 + i) * Dq + d0 + dg*4) = o;
    }
}

// ---------------- LayerNorm of (a+b): two-pass, fp64 accumulators
__global__ void ln_kernel(const float* __restrict__ a, const float* __restrict__ b,
                          const float* __restrict__ g, const float* __restrict__ be,
                          float* __restrict__ out)
{
    __shared__ double red[10];
    int row = blockIdx.x, tid = threadIdx.x;
    const float* pa = a + (size_t)row * Dq;
    const float* pb = b + (size_t)row * Dq;
    float v[3];
    double s = 0.0;
    #pragma unroll
    for (int i = 0; i < 3; i++) {
        float x = pa[tid + 256*i] + pb[tid + 256*i];
        v[i] = x; s += (double)x;
    }
    #pragma unroll
    for (int o = 16; o; o >>= 1) s += __shfl_down_sync(0xffffffffu, s, o);
    if ((tid & 31) == 0) red[tid >> 5] = s;
    __syncthreads();
    if (tid == 0) {
        double t = 0.0;
        #pragma unroll
        for (int w = 0; w < 8; w++) t += red[w];
        red[8] = t * (1.0/768.0);
    }
    __syncthreads();
    float mean = (float)red[8];

    double s2 = 0.0;
    #pragma unroll
    for (int i = 0; i < 3; i++) {
        double d = (double)v[i] - red[8];
        s2 += d * d;
    }
    #pragma unroll
    for (int o = 16; o; o >>= 1) s2 += __shfl_down_sync(0xffffffffu, s2, o);
    if ((tid & 31) == 0) red[tid >> 5] = s2;
    __syncthreads();
    if (tid == 0) {
        double t = 0.0;
        #pragma unroll
        for (int w = 0; w < 8; w++) t += red[w];
        red[9] = 1.0 / sqrt(t * (1.0/768.0) + 1e-5);
    }
    __syncthreads();
    float rs = (float)red[9];
    #pragma unroll
    for (int i = 0; i < 3; i++) {
        int c = tid + 256*i;
        out[(size_t)row * Dq + c] = (v[i] - mean) * rs * g[c] + be[c];
    }
}

// ---------------- RoPE (output tf32-rounded: only consumed by q/k GEMMs)
__global__ void rope_kernel(const float* __restrict__ x, const float* __restrict__ sn,
                            const float* __restrict__ cs, float* __restrict__ out)
{
    int idx = blockIdx.x * blockDim.x + threadIdx.x;
    if (idx >= ROWS * 384) return;
    int d = idx % 384, row = idx / 384, l = row & (Lq - 1);
    float x1 = x[(size_t)row * Dq + d];
    float x2 = x[(size_t)row * Dq + 384 + d];
    float sv = sn[l * 384 + d], cv = cs[l * 384 + d];
    out[(size_t)row * Dq + d]        = tf32r(x1 * cv - x2 * sv);
    out[(size_t)row * Dq + 384 + d]  = tf32r(x2 * cv + x1 * sv);
}

// ---------------- tensor-core flash attention, hd=64
// Q/K/V arrive tf32-rounded (qkv GEMM epilogue). Output tf32-rounded (feeds wo GEMM).
#define ATS 68
#define VTS 72
#define ATT_SMEM ((2*64*ATS + 64*VTS)*4)
__global__ void __launch_bounds__(128) attn_mma(
    const float* __restrict__ Q, const float* __restrict__ K,
    const float* __restrict__ V, float* __restrict__ O)
{
    extern __shared__ float sm[];
    float* Qs = sm;                 // 64 x ATS
    float* Ks = sm + 64*ATS;        // 64 x ATS; reused as P
    float* Vs = sm + 2*64*ATS;      // 64 x VTS
    const int tid = threadIdx.x;
    const int warp = tid >> 5, lane = tid & 31;
    const int g = lane >> 2, tc = lane & 3;
    const int bh = blockIdx.y;
    const int b = bh / Hq, h = bh % Hq;
    const int q0 = blockIdx.x * 64;
    const size_t base = (size_t)b * Lq * Dq + (size_t)h * 64;
    const int rlo = warp*16 + g;         // rows rlo, rlo+8

    for (int i = tid; i < 64*16; i += 128) {
        int rr = i >> 4, c4 = (i & 15) * 4;
        *(float4*)&Qs[rr*ATS + c4] = *(const float4*)(Q + base + (size_t)(q0 + rr) * Dq + c4);
    }

    float m0r = -INFINITY, m1r = -INFINITY, l0 = 0.f, l1 = 0.f;
    float o[8][4];
    #pragma unroll
    for (int ni = 0; ni < 8; ni++)
        #pragma unroll
        for (int j = 0; j < 4; j++) o[ni][j] = 0.f;

    for (int kt = 0; kt < Lq/64; ++kt) {
        __syncthreads();   // Vs/Ks(P) from prev iter fully consumed
        for (int i = tid; i < 64*16; i += 128) {
            int rr = i >> 4, c4 = (i & 15) * 4;
            *(float4*)&Ks[rr*ATS + c4] = *(const float4*)(K + base + (size_t)(kt*64 + rr) * Dq + c4);
            *(float4*)&Vs[rr*VTS + c4] = *(const float4*)(V + base + (size_t)(kt*64 + rr) * Dq + c4);
        }
        __syncthreads();

        // stage 1: S = Q @ K^T  (M=64 rows this warp: rlo block, N=64 keys, K=64)
        float s[8][4];
        #pragma unroll
        for (int ni = 0; ni < 8; ni++)
            #pragma unroll
            for (int j = 0; j < 4; j++) s[ni][j] = 0.f;
        #pragma unroll
        for (int k8 = 0; k8 < 64; k8 += 8) {
            uint32_t a0 = __float_as_uint(Qs[(warp*16 + g)*ATS + k8 + tc]);
            uint32_t a1 = __float_as_uint(Qs[(warp*16 + g + 8)*ATS + k8 + tc]);
            uint32_t a2 = __float_as_uint(Qs[(warp*16 + g)*ATS + k8 + tc + 4]);
            uint32_t a3 = __float_as_uint(Qs[(warp*16 + g + 8)*ATS + k8 + tc + 4]);
            #pragma unroll
            for (int ni = 0; ni < 8; ni++) {
                uint32_t b0 = __float_as_uint(Ks[(ni*8 + g)*ATS + k8 + tc]);
                uint32_t b1 = __float_as_uint(Ks[(ni*8 + g)*ATS + k8 + tc + 4]);
                asm volatile(
                    "mma.sync.aligned.m16n8k8.row.col.f32.tf32.tf32.f32 "
                    "{%0,%1,%2,%3}, {%4,%5,%6,%7}, {%8,%9}, {%0,%1,%2,%3};"
                    : "+f"(s[ni][0]), "+f"(s[ni][1]), "+f"(s[ni][2]), "+f"(s[ni][3])
                    : "r"(a0), "r"(a1), "r"(a2), "r"(a3), "r"(b0), "r"(b1));
            }
        }
        #pragma unroll
        for (int ni = 0; ni < 8; ni++)
            #pragma unroll
            for (int j = 0; j < 4; j++) s[ni][j] *= 0.125f;

        // softmax: rows rlo (s[.][0..1]) and rlo+8 (s[.][2..3]); lanes 4g+tc share row
        float mx0 = -INFINITY, mx1 = -INFINITY;
        #pragma unroll
        for (int ni = 0; ni < 8; ni++) {
            mx0 = fmaxf(mx0, fmaxf(s[ni][0], s[ni][1]));
            mx1 = fmaxf(mx1, fmaxf(s[ni][2], s[ni][3]));
        }
        mx0 = fmaxf(mx0, __shfl_xor_sync(0xffffffffu, mx0, 1));
        mx0 = fmaxf(mx0, __shfl_xor_sync(0xffffffffu, mx0, 2));
        mx1 = fmaxf(mx1, __shfl_xor_sync(0xffffffffu, mx1, 1));
        mx1 = fmaxf(mx1, __shfl_xor_sync(0xffffffffu, mx1, 2));
        float mn0 = fmaxf(m0r, mx0), mn1 = fmaxf(m1r, mx1);
        float ps0 = 0.f, ps1 = 0.f;
        #pragma unroll
        for (int ni = 0; ni < 8; ni++) {
            s[ni][0] = expf(s[ni][0] - mn0); ps0 += s[ni][0];
            s[ni][1] = expf(s[ni][1] - mn0); ps0 += s[ni][1];
            s[ni][2] = expf(s[ni][2] - mn1); ps1 += s[ni][2];
            s[ni][3] = expf(s[ni][3] - mn1); ps1 += s[ni][3];
        }
        ps0 += __shfl_xor_sync(0xffffffffu, ps0, 1);
        ps0 += __shfl_xor_sync(0xffffffffu, ps0, 2);
        ps1 += __shfl_xor_sync(0xffffffffu, ps1, 1);
        ps1 += __shfl_xor_sync(0xffffffffu, ps1, 2);
        float al0 = expf(m0r - mn0), al1 = expf(m1r - mn1);
        l0 = l0 * al0 + ps0;  m0r = mn0;
        l1 = l1 * al1 + ps1;  m1r = mn1;
        #pragma unroll
        for (int ni = 0; ni < 8; ni++) {
            o[ni][0] *= al0; o[ni][1] *= al0;
            o[ni][2] *= al1; o[ni][3] *= al1;
        }

        __syncthreads();   // all warps done reading Ks
        #pragma unroll
        for (int ni = 0; ni < 8; ni++) {
            *(float2*)&Ks[rlo*ATS + ni*8 + 2*tc] =
                make_float2(tf32r(s[ni][0]), tf32r(s[ni][1]));
            *(float2*)&Ks[(rlo+8)*ATS + ni*8 + 2*tc] =
                make_float2(tf32r(s[ni][2]), tf32r(s[ni][3]));
        }
        __syncthreads();

        // stage 2: O += P @ V  (K-dim = 64 keys)
        #pragma unroll
        for (int k8 = 0; k8 < 64; k8 += 8) {
            uint32_t a0 = __float_as_uint(Ks[(warp*16 + g)*ATS + k8 + tc]);
            uint32_t a1 = __float_as_uint(Ks[(warp*16 + g + 8)*ATS + k8 + tc]);
            uint32_t a2 = __float_as_uint(Ks[(warp*16 + g)*ATS + k8 + tc + 4]);
            uint32_t a3 = __float_as_uint(Ks[(warp*16 + g + 8)*ATS + k8 + tc + 4]);
            #pragma unroll
            for (int ni = 0; ni < 8; ni++) {
                uint32_t b0 = __float_as_uint(Vs[(k8 + tc)*VTS + ni*8 + g]);
                uint32_t b1 = __float_as_uint(Vs[(k8 + tc + 4)*VTS + ni*8 + g]);
                asm volatile(
                    "mma.sync.aligned.m16n8k8.row.col.f32.tf32.tf32.f32 "
                    "{%0,%1,%2,%3}, {%4,%5,%6,%7}, {%8,%9}, {%0,%1,%2,%3};"
                    : "+f"(o[ni][0]), "+f"(o[ni][1]), "+f"(o[ni][2]), "+f"(o[ni][3])
                    : "r"(a0), "r"(a1), "r"(a2), "r"(a3), "r"(b0), "r"(b1));
            }
        }
    }

    float inv0 = 1.f / l0, inv1 = 1.f / l1;
    #pragma unroll
    for (int ni = 0; ni < 8; ni++) {
        *(float2*)(O + base + (size_t)(q0 + rlo) * Dq + ni*8 + 2*tc) =
            make_float2(tf32r(o[ni][0]*inv0), tf32r(o[ni][1]*inv0));
        *(float2*)(O + base + (size_t)(q0 + rlo + 8) * Dq + ni*8 + 2*tc) =
            make_float2(tf32r(o[ni][2]*inv1), tf32r(o[ni][3]*inv1));
    }
}

// ---------------- host orchestration ----------------
extern "C" void kernel_launch(void* const* d_in, const int* in_sizes, int n_in,
                              void* d_out, int out_size)
{
    (void)n_in; (void)out_size;
    const float* x   = (const float*)d_in[0];
    const float* sn  = (const float*)d_in[1];
    const float* cs  = (const float*)d_in[2];
    const float* w1s[3] = {(const float*)d_in[3], (const float*)d_in[7],  (const float*)d_in[11]};
    const float* b1s[3] = {(const float*)d_in[4], (const float*)d_in[8],  (const float*)d_in[12]};
    const float* w2s[3] = {(const float*)d_in[5], (const float*)d_in[9],  (const float*)d_in[13]};
    const float* b2s[3] = {(const float*)d_in[6], (const float*)d_in[10], (const float*)d_in[14]};
    const float* ln1g = (const float*)d_in[15];
    const float* ln1b = (const float*)d_in[16];
    const float* ln2g = (const float*)d_in[17];
    const float* ln2b = (const float*)d_in[18];

    const float *wq, *bqv, *wk, *bkv, *wv, *bvv, *wo, *bov;
    if (in_sizes[20] == 768) {
        wq = (const float*)d_in[19]; bqv = (const float*)d_in[20];
        wk = (const float*)d_in[21]; bkv = (const float*)d_in[22];
        wv = (const float*)d_in[23]; bvv = (const float*)d_in[24];
        wo = (const float*)d_in[25]; bov = (const float*)d_in[26];
    } else {
        wq = (const float*)d_in[19]; wk  = (const float*)d_in[20];
        wv = (const float*)d_in[21]; wo  = (const float*)d_in[22];
        bqv = (const float*)d_in[23]; bkv = (const float*)d_in[24];
        bvv = (const float*)d_in[25]; bov = (const float*)d_in[26];
    }
    const float* mw1 = (const float*)d_in[27]; const float* mb1 = (const float*)d_in[28];
    const float* mw2 = (const float*)d_in[29]; const float* mb2 = (const float*)d_in[30];

    float *t1, *pp, *ha, *hb, *gx, *gqk, *gq, *gk, *gv, *gatt, *go, *gx2, *wr;
    cudaGetSymbolAddress((void**)&t1,  g_t1);
    cudaGetSymbolAddress((void**)&pp,  g_p);
    cudaGetSymbolAddress((void**)&ha,  g_ha);
    cudaGetSymbolAddress((void**)&hb,  g_hb);
    cudaGetSymbolAddress((void**)&gx,  g_x);
    cudaGetSymbolAddress((void**)&gqk, g_qk);
    cudaGetSymbolAddress((void**)&gq,  g_q);
    cudaGetSymbolAddress((void**)&gk,  g_k);
    cudaGetSymbolAddress((void**)&gv,  g_v);
    cudaGetSymbolAddress((void**)&gatt,g_att);
    cudaGetSymbolAddress((void**)&go,  g_o);
    cudaGetSymbolAddress((void**)&gx2, g_x2);
    cudaGetSymbolAddress((void**)&wr,  g_wr);

    // ---- pre-round weights into scratch (B operands never cvt in GEMM) ----
    const float* srcW[10] = {w1s[0], w1s[1], w1s[2], w2s[0], w2s[1], w2s[2],
                             wq, wk, wv, wo};
    const int    szW[10]  = {768*3072, 768*3072, 768*3072,
                             3072*14, 3072*384, 3072*1024,
                             589824, 589824, 589824, 589824};
    float* dstW[12];
    {
        size_t ofs = 0;
        for (int i = 0; i < 10; i++) {
            dstW[i] = wr + ofs; ofs += szW[i];
            int n4 = szW[i] / 4;
            round_copy<<<(n4 + 255)/256, 256>>>((const float4*)srcW[i], (float4*)dstW[i], n4);
        }
        dstW[10] = wr + ofs; ofs += (size_t)768*3072;   // mw1
        dstW[11] = wr + ofs;                             // mw2
        int n4 = 768*3072/4;
        round_copy<<<(n4 + 255)/256, 256>>>((const float4*)mw1, (float4*)dstW[10], n4);
        n4 = 3072*768/4;
        round_copy<<<(n4 + 255)/256, 256>>>((const float4*)mw2, (float4*)dstW[11], n4);
    }
    const float* rw1[3] = {dstW[0], dstW[1], dstW[2]};
    const float* rw2[3] = {dstW[3], dstW[4], dstW[5]};
    const float *rwq = dstW[6], *rwk = dstW[7], *rwv = dstW[8], *rwo = dstW[9];
    const float *rmw1 = dstW[10], *rmw2 = dstW[11];

    cudaFuncSetAttribute(gemm_tc<1,0,1,1>, cudaFuncAttributeMaxDynamicSharedMemorySize, GEMM_SMEM);
    cudaFuncSetAttribute(gemm_tc<0,0,0,0>, cudaFuncAttributeMaxDynamicSharedMemorySize, GEMM_SMEM);
    cudaFuncSetAttribute(gemm_tc<0,1,0,0>, cudaFuncAttributeMaxDynamicSharedMemorySize, GEMM_SMEM);
    cudaFuncSetAttribute(gemm_qkv,         cudaFuncAttributeMaxDynamicSharedMemorySize, GEMM_SMEM);
    cudaFuncSetAttribute(conv_tiled<128>,  cudaFuncAttributeMaxDynamicSharedMemorySize, CONV_SMEM);
    cudaFuncSetAttribute(conv_tiled<256>,  cudaFuncAttributeMaxDynamicSharedMemorySize, CONV_SMEM);
    cudaFuncSetAttribute(attn_mma,         cudaFuncAttributeMaxDynamicSharedMemorySize, ATT_SMEM);

    cudaMemcpyAsync(ha, x, sizeof(float)*(size_t)ROWS*Dq, cudaMemcpyDeviceToDevice);

    const int orderF[3] = {14, 384, 1024};
    const int Fs[3]     = {7, 128, 256};
    const int ords[3]   = {2, 3, 4};

    float* hc = ha; float* hn = hb;
    const int convBlocks = (ROWS * (Dq/4) + 255) / 256;

    for (int s3 = 0; s3 < 3; s3++) {
        gemm_tc<1,0,1,1><<<dim3(24,32), 256, GEMM_SMEM>>>(hc, rw1[s3], b1s[s3], nullptr, t1, 3072, 768);
        gemm_tc<0,0,0,0><<<dim3((orderF[s3]+127)/128, 32), 256, GEMM_SMEM>>>(t1, rw2[s3], b2s[s3], nullptr, pp, orderF[s3], 3072);
        for (int i = 0; i < ords[s3]; i++) {
            if (Fs[s3] == 7)
                conv_gelu<<<convBlocks, 256>>>(hc, pp, hn, 7, orderF[s3], i * 7);
            else if (Fs[s3] == 128)
                conv_tiled<128><<<dim3(12,64), 256, CONV_SMEM>>>(hc, pp, hn, orderF[s3], i * 128);
            else
                conv_tiled<256><<<dim3(12,64), 256, CONV_SMEM>>>(hc, pp, hn, orderF[s3], i * 256);
            float* tmp = hc; hc = hn; hn = tmp;
        }
    }

    ln_kernel<<<ROWS, 256>>>(x, hc, ln1g, ln1b, gx);
    rope_kernel<<<(ROWS*384 + 255)/256, 256>>>(gx, sn, cs, gqk);

    gemm_qkv<<<dim3(6,32,3), 256, GEMM_SMEM>>>(gqk, gx, rwq, bqv, gq, rwk, bkv, gk, rwv, bvv, gv);

    attn_mma<<<dim3(Lq/64, Bq*Hq), 128, ATT_SMEM>>>(gq, gk, gv, gatt);

    gemm_tc<0,0,0,0><<<dim3(6,32), 256, GEMM_SMEM>>>(gatt, rwo, bov, nullptr, go, 768, 768);
    ln_kernel<<<ROWS, 256>>>(gx, go, ln2g, ln2b, gx2);
    gemm_tc<1,0,1,1><<<dim3(24,32), 256, GEMM_SMEM>>>(gx2, rmw1, mb1, nullptr, t1, 3072, 768);
    gemm_tc<0,1,0,0><<<dim3(6,32), 256, GEMM_SMEM>>>(t1, rmw2, mb2, gx2, (float*)d_out, 768, 3072);
}

// round 8
// speedup vs baseline: 4.8450x; 1.0475x over previous
#include <cuda_runtime.h>
#include <math.h>
#include <stdint.h>

#define Bq 2
#define Lq 2048
#define Dq 768
#define Hq 12
#define ROWS (Bq*Lq)   /* 4096 */

// ---------------- scratch (device globals; no allocation allowed) ----------------
__device__ float g_t1[(size_t)ROWS*3072];
__device__ float g_p [(size_t)ROWS*1024];
__device__ float g_ha[(size_t)ROWS*Dq];
__device__ float g_hb[(size_t)ROWS*Dq];
__device__ float g_x [(size_t)ROWS*Dq];
__device__ float g_qk[(size_t)ROWS*Dq];
__device__ float g_q [(size_t)ROWS*Dq];
__device__ float g_k [(size_t)ROWS*Dq];
__device__ float g_v [(size_t)ROWS*Dq];
__device__ float g_att[(size_t)ROWS*Dq];
__device__ float g_o [(size_t)ROWS*Dq];
__device__ float g_x2[(size_t)ROWS*Dq];
__device__ float g_wr[18524160];   // pre-rounded weights (74MB), contiguous

__device__ __forceinline__ float gelu_f(float x){
    return 0.5f*x*(1.0f+erff(x*0.70710678118654752440f));
}
__device__ __forceinline__ uint32_t tf32u(float x){
    uint32_t u;
    asm("cvt.rna.tf32.f32 %0, %1;" : "=r"(u) : "f"(x));
    return u;
}
__device__ __forceinline__ float tf32r(float x){
    return __uint_as_float(tf32u(x));
}
__device__ __forceinline__ void cp16(uint32_t smem_dst, const void* gsrc){
    asm volatile("cp.async.ca.shared.global [%0], [%1], 16;\n"
                 :: "r"(smem_dst), "l"(gsrc));
}

// ---------------- merged tf32 round-copy of all 12 weight matrices ----------------
struct WSrc { const float4* s[12]; };
#define W_TOTAL4 4631040
__global__ void round_all(WSrc w, float4* __restrict__ dst)
{
    // segment ends in float4 units (prefix over: w1a,w1b,w1c,w2a,w2b,w2c,wq,wk,wv,wo,mw1,mw2)
    const int end4[12] = {589824, 1179648, 1769472, 1780224, 2075136, 2861568,
                          3009024, 3156480, 3303936, 3451392, 4041216, 4631040};
    int i = blockIdx.x * blockDim.x + threadIdx.x;
    if (i >= W_TOTAL4) return;
    int s = 0;
    #pragma unroll
    for (int k = 0; k < 12; k++) if (i >= end4[k]) s = k + 1;
    int st = (s == 0) ? 0 : end4[s-1];
    float4 v = w.s[s][i - st];
    dst[i] = make_float4(tf32r(v.x), tf32r(v.y), tf32r(v.z), tf32r(v.w));
}

// ---------------- tensor-core TF32 GEMM body, 2-stage cp.async pipeline
// C = A(4096xK)@B(KxN) + bias [,GELU][,+Res][,tf32-round-out]; K mult of 32.
// B must be pre-rounded to tf32. A rounded at frag load iff CVTA.
#define GEMM_SMEM (2*(128*36 + 32*136)*4)
template<int GELU, int RES, int CVTA, int ROUT>
__device__ __forceinline__ void gemm_body(
    const float* __restrict__ A, const float* __restrict__ Bm,
    const float* __restrict__ bias, const float* __restrict__ Rr,
    float* __restrict__ C, int N, int K)
{
    extern __shared__ uint32_t smem_u[];
    uint32_t* AsB = smem_u;
    uint32_t* BsB = smem_u + 2*128*36;
    const int tid  = threadIdx.x;
    const int warp = tid >> 5, lane = tid & 31;
    const int g = lane >> 2, tc = lane & 3;
    const int wm0 = (warp & 1) * 64, wn0 = (warp >> 1) * 32;
    const int row0 = blockIdx.y * 128, col0 = blockIdx.x * 128;
    const bool colFull = (col0 + 128 <= N);

    float acc[4][4][4] = {};
    const int ar = tid >> 3,  ac = (tid & 7) * 4;
    const int bk = tid >> 5,  bc = (tid & 31) * 4;
    const int nt = K / 32;

    auto issue = [&](int kt, int s){
        uint32_t* as = AsB + s * (128*36);
        uint32_t* bs = BsB + s * (32*136);
        const int k0 = kt * 32;
        #pragma unroll
        for (int p = 0; p < 4; p++) {
            int r = ar + p * 32;
            cp16((uint32_t)__cvta_generic_to_shared(&as[r*36 + ac]),
                 A + (size_t)(row0 + r) * K + k0 + ac);
        }
        if (colFull) {
            #pragma unroll
            for (int p = 0; p < 4; p++) {
                int kr = bk + p * 8;
                cp16((uint32_t)__cvta_generic_to_shared(&bs[kr*136 + bc]),
                     Bm + (size_t)(k0 + kr) * N + col0 + bc);
            }
        } else {
            #pragma unroll
            for (int p = 0; p < 4; p++) {
                int kr = bk + p * 8;
                #pragma unroll
                for (int u = 0; u < 4; u++) {
                    int c = col0 + bc + u;
                    bs[kr*136 + bc + u] =
                        (c < N) ? __float_as_uint(Bm[(size_t)(k0 + kr) * N + c]) : 0u;
                }
            }
        }
        asm volatile("cp.async.commit_group;\n");
    };

    issue(0, 0);
    for (int kt = 0; kt < nt; kt++) {
        const int cur = kt & 1;
        if (kt + 1 < nt) {
            issue(kt + 1, cur ^ 1);
            asm volatile("cp.async.wait_group 1;\n");
        } else {
            asm volatile("cp.async.wait_group 0;\n");
        }
        __syncthreads();
        const uint32_t* as = AsB + cur * (128*36);
        const uint32_t* bs = BsB + cur * (32*136);
        #pragma unroll
        for (int k8 = 0; k8 < 32; k8 += 8) {
            uint32_t af[4][4], bf[4][2];
            #pragma unroll
            for (int mi = 0; mi < 4; mi++) {
                const uint32_t* base = &as[(wm0 + mi*16 + g) * 36 + k8 + tc];
                if (CVTA) {
                    af[mi][0] = tf32u(__uint_as_float(base[0]));
                    af[mi][1] = tf32u(__uint_as_float(base[8*36]));
                    af[mi][2] = tf32u(__uint_as_float(base[4]));
                    af[mi][3] = tf32u(__uint_as_float(base[8*36 + 4]));
                } else {
                    af[mi][0] = base[0];
                    af[mi][1] = base[8*36];
                    af[mi][2] = base[4];
                    af[mi][3] = base[8*36 + 4];
                }
            }
            #pragma unroll
            for (int ni = 0; ni < 4; ni++) {
                const uint32_t* base = &bs[(k8 + tc) * 136 + wn0 + ni*8 + g];
                bf[ni][0] = base[0];
                bf[ni][1] = base[4*136];
            }
            #pragma unroll
            for (int mi = 0; mi < 4; mi++)
                #pragma unroll
                for (int ni = 0; ni < 4; ni++)
                    asm volatile(
                        "mma.sync.aligned.m16n8k8.row.col.f32.tf32.tf32.f32 "
                        "{%0,%1,%2,%3}, {%4,%5,%6,%7}, {%8,%9}, {%0,%1,%2,%3};"
                        : "+f"(acc[mi][ni][0]), "+f"(acc[mi][ni][1]),
                          "+f"(acc[mi][ni][2]), "+f"(acc[mi][ni][3])
                        : "r"(af[mi][0]), "r"(af[mi][1]), "r"(af[mi][2]), "r"(af[mi][3]),
                          "r"(bf[ni][0]), "r"(bf[ni][1]));
        }
        __syncthreads();
    }

    #pragma unroll
    for (int mi = 0; mi < 4; mi++) {
        int r0 = row0 + wm0 + mi*16 + g;
        #pragma unroll
        for (int ni = 0; ni < 4; ni++) {
            int c = col0 + wn0 + ni*8 + tc*2;
            if (c < N) {
                float b0 = bias[c], b1 = bias[c+1];
                float v0 = acc[mi][ni][0] + b0, v1 = acc[mi][ni][1] + b1;
                float v2 = acc[mi][ni][2] + b0, v3 = acc[mi][ni][3] + b1;
                if (GELU) { v0 = gelu_f(v0); v1 = gelu_f(v1); v2 = gelu_f(v2); v3 = gelu_f(v3); }
                if (ROUT) { v0 = tf32r(v0); v1 = tf32r(v1); v2 = tf32r(v2); v3 = tf32r(v3); }
                if (RES) {
                    v0 += Rr[(size_t)r0*N + c];     v1 += Rr[(size_t)r0*N + c + 1];
                    v2 += Rr[(size_t)(r0+8)*N + c]; v3 += Rr[(size_t)(r0+8)*N + c + 1];
                }
                *(float2*)(C + (size_t)r0*N + c)     = make_float2(v0, v1);
                *(float2*)(C + (size_t)(r0+8)*N + c) = make_float2(v2, v3);
            }
        }
    }
}

template<int GELU, int RES, int CVTA, int ROUT>
__global__ void __launch_bounds__(256, 2) gemm_tc(
    const float* __restrict__ A, const float* __restrict__ Bm,
    const float* __restrict__ bias, const float* __restrict__ Rr,
    float* __restrict__ C, int N, int K)
{
    gemm_body<GELU, RES, CVTA, ROUT>(A, Bm, bias, Rr, C, N, K);
}

// ---------------- split-K TF32 GEMM: C += chunk contribution via atomicAdd.
// C must be pre-zeroed. Chunk z (blockIdx.z) covers k in [z*KC, (z+1)*KC).
// bias (+ residual if RES) folded into chunk 0. A and B pre-rounded (CVTA=0).
template<int RES>
__global__ void __launch_bounds__(256, 2) gemm_tc_sk(
    const float* __restrict__ A, const float* __restrict__ Bm,
    const float* __restrict__ bias, const float* __restrict__ Rr,
    float* __restrict__ C, int N, int K, int KC)
{
    extern __shared__ uint32_t smem_u[];
    uint32_t* AsB = smem_u;
    uint32_t* BsB = smem_u + 2*128*36;
    const int tid  = threadIdx.x;
    const int warp = tid >> 5, lane = tid & 31;
    const int g = lane >> 2, tc = lane & 3;
    const int wm0 = (warp & 1) * 64, wn0 = (warp >> 1) * 32;
    const int row0 = blockIdx.y * 128, col0 = blockIdx.x * 128;
    const int z = blockIdx.z;
    const int kbase = z * KC;
    const bool colFull = (col0 + 128 <= N);

    float acc[4][4][4] = {};
    const int ar = tid >> 3,  ac = (tid & 7) * 4;
    const int bk = tid >> 5,  bc = (tid & 31) * 4;
    const int nt = KC / 32;

    auto issue = [&](int kt, int s){
        uint32_t* as = AsB + s * (128*36);
        uint32_t* bs = BsB + s * (32*136);
        const int k0 = kbase + kt * 32;
        #pragma unroll
        for (int p = 0; p < 4; p++) {
            int r = ar + p * 32;
            cp16((uint32_t)__cvta_generic_to_shared(&as[r*36 + ac]),
                 A + (size_t)(row0 + r) * K + k0 + ac);
        }
        if (colFull) {
            #pragma unroll
            for (int p = 0; p < 4; p++) {
                int kr = bk + p * 8;
                cp16((uint32_t)__cvta_generic_to_shared(&bs[kr*136 + bc]),
                     Bm + (size_t)(k0 + kr) * N + col0 + bc);
            }
        } else {
            #pragma unroll
            for (int p = 0; p < 4; p++) {
                int kr = bk + p * 8;
                #pragma unroll
                for (int u = 0; u < 4; u++) {
                    int c = col0 + bc + u;
                    bs[kr*136 + bc + u] =
                        (c < N) ? __float_as_uint(Bm[(size_t)(k0 + kr) * N + c]) : 0u;
                }
            }
        }
        asm volatile("cp.async.commit_group;\n");
    };

    issue(0, 0);
    for (int kt = 0; kt < nt; kt++) {
        const int cur = kt & 1;
        if (kt + 1 < nt) {
            issue(kt + 1, cur ^ 1);
            asm volatile("cp.async.wait_group 1;\n");
        } else {
            asm volatile("cp.async.wait_group 0;\n");
        }
        __syncthreads();
        const uint32_t* as = AsB + cur * (128*36);
        const uint32_t* bs = BsB + cur * (32*136);
        #pragma unroll
        for (int k8 = 0; k8 < 32; k8 += 8) {
            uint32_t af[4][4], bf[4][2];
            #pragma unroll
            for (int mi = 0; mi < 4; mi++) {
                const uint32_t* base = &as[(wm0 + mi*16 + g) * 36 + k8 + tc];
                af[mi][0] = base[0];
                af[mi][1] = base[8*36];
                af[mi][2] = base[4];
                af[mi][3] = base[8*36 + 4];
            }
            #pragma unroll
            for (int ni = 0; ni < 4; ni++) {
                const uint32_t* base = &bs[(k8 + tc) * 136 + wn0 + ni*8 + g];
                bf[ni][0] = base[0];
                bf[ni][1] = base[4*136];
            }
            #pragma unroll
            for (int mi = 0; mi < 4; mi++)
                #pragma unroll
                for (int ni = 0; ni < 4; ni++)
                    asm volatile(
                        "mma.sync.aligned.m16n8k8.row.col.f32.tf32.tf32.f32 "
                        "{%0,%1,%2,%3}, {%4,%5,%6,%7}, {%8,%9}, {%0,%1,%2,%3};"
                        : "+f"(acc[mi][ni][0]), "+f"(acc[mi][ni][1]),
                          "+f"(acc[mi][ni][2]), "+f"(acc[mi][ni][3])
                        : "r"(af[mi][0]), "r"(af[mi][1]), "r"(af[mi][2]), "r"(af[mi][3]),
                          "r"(bf[ni][0]), "r"(bf[ni][1]));
        }
        __syncthreads();
    }

    const bool lead = (z == 0);
    #pragma unroll
    for (int mi = 0; mi < 4; mi++) {
        int r0 = row0 + wm0 + mi*16 + g;
        #pragma unroll
        for (int ni = 0; ni < 4; ni++) {
            int c = col0 + wn0 + ni*8 + tc*2;
            if (c < N) {
                float v0 = acc[mi][ni][0], v1 = acc[mi][ni][1];
                float v2 = acc[mi][ni][2], v3 = acc[mi][ni][3];
                if (lead) {
                    float b0 = bias[c], b1 = bias[c+1];
                    v0 += b0; v1 += b1; v2 += b0; v3 += b1;
                    if (RES) {
                        v0 += Rr[(size_t)r0*N + c];     v1 += Rr[(size_t)r0*N + c + 1];
                        v2 += Rr[(size_t)(r0+8)*N + c]; v3 += Rr[(size_t)(r0+8)*N + c + 1];
                    }
                }
                atomicAdd(C + (size_t)r0*N + c,       v0);
                atomicAdd(C + (size_t)r0*N + c + 1,   v1);
                atomicAdd(C + (size_t)(r0+8)*N + c,   v2);
                atomicAdd(C + (size_t)(r0+8)*N + c+1, v3);
            }
        }
    }
}

// fused q/k/v projection: blockIdx.z selects {q,k,v}; outputs tf32-rounded
__global__ void __launch_bounds__(256, 2) gemm_qkv(
    const float* __restrict__ gqk, const float* __restrict__ gx,
    const float* __restrict__ wq, const float* __restrict__ bq, float* __restrict__ oq,
    const float* __restrict__ wk, const float* __restrict__ bk, float* __restrict__ ok,
    const float* __restrict__ wv, const float* __restrict__ bv, float* __restrict__ ov)
{
    const int z = blockIdx.z;
    if (z == 2) {
        gemm_body<0,0,1,1>(gx, wv, bv, nullptr, ov, 768, 768);
    } else if (z == 1) {
        gemm_body<0,0,0,1>(gqk, wk, bk, nullptr, ok, 768, 768);
    } else {
        gemm_body<0,0,0,1>(gqk, wq, bq, nullptr, oq, 768, 768);
    }
}

// ---------------- direct conv (F=7 only) + GELU, fp32, m descending
__global__ void conv_gelu(const float* __restrict__ h, const float* __restrict__ p,
                          float* __restrict__ out, int F, int pstride, int poff)
{
    int idx = blockIdx.x * blockDim.x + threadIdx.x;
    if (idx >= ROWS * (Dq/4)) return;
    int d4 = idx % (Dq/4);
    int bt = idx / (Dq/4);
    int t  = bt & (Lq - 1);
    const float* kr = p + (size_t)bt * pstride + poff;
    int mmax = min(F - 1, t);
    float ax = 0.f, ay = 0.f, az = 0.f, aw = 0.f;
    for (int m = mmax; m >= 0; --m) {
        float kv = __ldg(kr + m);
        const float4 hv = *(const float4*)(h + (size_t)(bt - m) * Dq + d4 * 4);
        ax = fmaf(kv, hv.x, ax);
        ay = fmaf(kv, hv.y, ay);
        az = fmaf(kv, hv.z, az);
        aw = fmaf(kv, hv.w, aw);
    }
    float4 o;
    o.x = gelu_f(ax); o.y = gelu_f(ay); o.z = gelu_f(az); o.w = gelu_f(aw);
    *(float4*)(out + (size_t)bt * Dq + d4 * 4) = o;
}

// ---------------- smem-tiled conv + GELU for F in {128, 256} (fp32 exact)
#define CONV_SMEM ((128*68 + 64*68)*4)
template<int F>
__global__ void __launch_bounds__(256) conv_tiled(
    const float* __restrict__ h, const float* __restrict__ p,
    float* __restrict__ out, int pstride, int poff)
{
    extern __shared__ float csm[];
    float* hs = csm;            // 128 x 68
    float* ps = csm + 128*68;   // 64 x 68
    const int tid = threadIdx.x;
    const int d0  = blockIdx.x * 64;
    const int bt0 = blockIdx.y * 64;
    const int batch = bt0 / Lq;
    const int t0    = bt0 & (Lq - 1);
    const int tg = tid >> 4;
    const int dg = tid & 15;

    float4 acc[4];
    #pragma unroll
    for (int i = 0; i < 4; i++) acc[i] = make_float4(0.f, 0.f, 0.f, 0.f);

    for (int m0 = F - 64; m0 >= 0; m0 -= 64) {
        for (int idx = tid; idx < 128*16; idx += 256) {
            int row = idx >> 4, c4 = (idx & 15) * 4;
            int lt = t0 - m0 - 64 + row;
            float4 v = make_float4(0.f, 0.f, 0.f, 0.f);
            if (lt >= 0)
                v = *(const float4*)(h + (size_t)(batch*Lq + lt) * Dq + d0 + c4);
            *(float4*)&hs[row*68 + c4] = v;
        }
        for (int idx = tid; idx < 64*16; idx += 256) {
            int row = idx >> 4, c4 = (idx & 15) * 4;
            float4 v = *(const float4*)(p + (size_t)(bt0 + row) * pstride + poff + m0 + c4);
            *(float4*)&ps[row*68 + c4] = v;
        }
        __syncthreads();
        #pragma unroll 4
        for (int mi = 63; mi >= 0; --mi) {
            #pragma unroll
            for (int i = 0; i < 4; i++) {
                float pk = ps[(tg*4 + i)*68 + mi];
                int rrow = tg*4 + i - mi + 64;
                float4 hv = *(const float4*)&hs[rrow*68 + dg*4];
                acc[i].x = fmaf(pk, hv.x, acc[i].x);
                acc[i].y = fmaf(pk, hv.y, acc[i].y);
                acc[i].z = fmaf(pk, hv.z, acc[i].z);
                acc[i].w = fmaf(pk, hv.w, acc[i].w);
            }
        }
        __syncthreads();
    }

    #pragma unroll
    for (int i = 0; i < 4; i++) {
        float4 o;
        o.x = gelu_f(acc[i].x); o.y = gelu_f(acc[i].y);
        o.z = gelu_f(acc[i].z); o.w = gelu_f(acc[i].w);
        *(float4*)(out + (size_t)(bt0 + tg*4 + i) * Dq + d0 + dg*4) = o;
    }
}

// ---------------- LayerNorm of (a+b): two-pass, fp64 accumulators
__global__ void ln_kernel(const float* __restrict__ a, const float* __restrict__ b,
                          const float* __restrict__ g, const float* __restrict__ be,
                          float* __restrict__ out)
{
    __shared__ double red[10];
    int row = blockIdx.x, tid = threadIdx.x;
    const float* pa = a + (size_t)row * Dq;
    const float* pb = b + (size_t)row * Dq;
    float v[3];
    double s = 0.0;
    #pragma unroll
    for (int i = 0; i < 3; i++) {
        float x = pa[tid + 256*i] + pb[tid + 256*i];
        v[i] = x; s += (double)x;
    }
    #pragma unroll
    for (int o = 16; o; o >>= 1) s += __shfl_down_sync(0xffffffffu, s, o);
    if ((tid & 31) == 0) red[tid >> 5] = s;
    __syncthreads();
    if (tid == 0) {
        double t = 0.0;
        #pragma unroll
        for (int w = 0; w < 8; w++) t += red[w];
        red[8] = t * (1.0/768.0);
    }
    __syncthreads();
    float mean = (float)red[8];

    double s2 = 0.0;
    #pragma unroll
    for (int i = 0; i < 3; i++) {
        double d = (double)v[i] - red[8];
        s2 += d * d;
    }
    #pragma unroll
    for (int o = 16; o; o >>= 1) s2 += __shfl_down_sync(0xffffffffu, s2, o);
    if ((tid & 31) == 0) red[tid >> 5] = s2;
    __syncthreads();
    if (tid == 0) {
        double t = 0.0;
        #pragma unroll
        for (int w = 0; w < 8; w++) t += red[w];
        red[9] = 1.0 / sqrt(t * (1.0/768.0) + 1e-5);
    }
    __syncthreads();
    float rs = (float)red[9];
    #pragma unroll
    for (int i = 0; i < 3; i++) {
        int c = tid + 256*i;
        out[(size_t)row * Dq + c] = (v[i] - mean) * rs * g[c] + be[c];
    }
}

// ---------------- fused LayerNorm(a+b) + RoPE: writes normalized row (ox)
// and tf32-rounded roped row (oqk).
__global__ void ln_rope_kernel(const float* __restrict__ a, const float* __restrict__ b,
                               const float* __restrict__ g, const float* __restrict__ be,
                               const float* __restrict__ sn, const float* __restrict__ cs,
                               float* __restrict__ ox, float* __restrict__ oqk)
{
    __shared__ double red[10];
    __shared__ float srow[768];
    int row = blockIdx.x, tid = threadIdx.x;
    int l = row & (Lq - 1);
    const float* pa = a + (size_t)row * Dq;
    const float* pb = b + (size_t)row * Dq;
    float v[3];
    double s = 0.0;
    #pragma unroll
    for (int i = 0; i < 3; i++) {
        float x = pa[tid + 256*i] + pb[tid + 256*i];
        v[i] = x; s += (double)x;
    }
    #pragma unroll
    for (int o = 16; o; o >>= 1) s += __shfl_down_sync(0xffffffffu, s, o);
    if ((tid & 31) == 0) red[tid >> 5] = s;
    __syncthreads();
    if (tid == 0) {
        double t = 0.0;
        #pragma unroll
        for (int w = 0; w < 8; w++) t += red[w];
        red[8] = t * (1.0/768.0);
    }
    __syncthreads();
    float mean = (float)red[8];

    double s2 = 0.0;
    #pragma unroll
    for (int i = 0; i < 3; i++) {
        double d = (double)v[i] - red[8];
        s2 += d * d;
    }
    #pragma unroll
    for (int o = 16; o; o >>= 1) s2 += __shfl_down_sync(0xffffffffu, s2, o);
    if ((tid & 31) == 0) red[tid >> 5] = s2;
    __syncthreads();
    if (tid == 0) {
        double t = 0.0;
        #pragma unroll
        for (int w = 0; w < 8; w++) t += red[w];
        red[9] = 1.0 / sqrt(t * (1.0/768.0) + 1e-5);
    }
    __syncthreads();
    float rs = (float)red[9];
    #pragma unroll
    for (int i = 0; i < 3; i++) {
        int c = tid + 256*i;
        float y = (v[i] - mean) * rs * g[c] + be[c];
        ox[(size_t)row * Dq + c] = y;
        srow[c] = y;
    }
    __syncthreads();
    #pragma unroll
    for (int i = 0; i < 3; i++) {
        int c = tid + 256*i;
        float r;
        if (c < 384) {
            float sv = sn[l*384 + c], cv = cs[l*384 + c];
            r = srow[c] * cv - srow[c + 384] * sv;
        } else {
            int d = c - 384;
            float sv = sn[l*384 + d], cv = cs[l*384 + d];
            r = srow[c] * cv + srow[d] * sv;
        }
        oqk[(size_t)row * Dq + c] = tf32r(r);
    }
}

// ---------------- tensor-core flash attention, hd=64
#define ATS 68
#define VTS 72
#define ATT_SMEM ((2*64*ATS + 64*VTS)*4)
__global__ void __launch_bounds__(128) attn_mma(
    const float* __restrict__ Q, const float* __restrict__ K,
    const float* __restrict__ V, float* __restrict__ O)
{
    extern __shared__ float sm[];
    float* Qs = sm;
    float* Ks = sm + 64*ATS;
    float* Vs = sm + 2*64*ATS;
    const int tid = threadIdx.x;
    const int warp = tid >> 5, lane = tid & 31;
    const int g = lane >> 2, tc = lane & 3;
    const int bh = blockIdx.y;
    const int b = bh / Hq, h = bh % Hq;
    const int q0 = blockIdx.x * 64;
    const size_t base = (size_t)b * Lq * Dq + (size_t)h * 64;
    const int rlo = warp*16 + g;

    for (int i = tid; i < 64*16; i += 128) {
        int rr = i >> 4, c4 = (i & 15) * 4;
        *(float4*)&Qs[rr*ATS + c4] = *(const float4*)(Q + base + (size_t)(q0 + rr) * Dq + c4);
    }

    float m0r = -INFINITY, m1r = -INFINITY, l0 = 0.f, l1 = 0.f;
    float o[8][4];
    #pragma unroll
    for (int ni = 0; ni < 8; ni++)
        #pragma unroll
        for (int j = 0; j < 4; j++) o[ni][j] = 0.f;

    for (int kt = 0; kt < Lq/64; ++kt) {
        __syncthreads();
        for (int i = tid; i < 64*16; i += 128) {
            int rr = i >> 4, c4 = (i & 15) * 4;
            *(float4*)&Ks[rr*ATS + c4] = *(const float4*)(K + base + (size_t)(kt*64 + rr) * Dq + c4);
            *(float4*)&Vs[rr*VTS + c4] = *(const float4*)(V + base + (size_t)(kt*64 + rr) * Dq + c4);
        }
        __syncthreads();

        float s[8][4];
        #pragma unroll
        for (int ni = 0; ni < 8; ni++)
            #pragma unroll
            for (int j = 0; j < 4; j++) s[ni][j] = 0.f;
        #pragma unroll
        for (int k8 = 0; k8 < 64; k8 += 8) {
            uint32_t a0 = __float_as_uint(Qs[(warp*16 + g)*ATS + k8 + tc]);
            uint32_t a1 = __float_as_uint(Qs[(warp*16 + g + 8)*ATS + k8 + tc]);
            uint32_t a2 = __float_as_uint(Qs[(warp*16 + g)*ATS + k8 + tc + 4]);
            uint32_t a3 = __float_as_uint(Qs[(warp*16 + g + 8)*ATS + k8 + tc + 4]);
            #pragma unroll
            for (int ni = 0; ni < 8; ni++) {
                uint32_t b0 = __float_as_uint(Ks[(ni*8 + g)*ATS + k8 + tc]);
                uint32_t b1 = __float_as_uint(Ks[(ni*8 + g)*ATS + k8 + tc + 4]);
                asm volatile(
                    "mma.sync.aligned.m16n8k8.row.col.f32.tf32.tf32.f32 "
                    "{%0,%1,%2,%3}, {%4,%5,%6,%7}, {%8,%9}, {%0,%1,%2,%3};"
                    : "+f"(s[ni][0]), "+f"(s[ni][1]), "+f"(s[ni][2]), "+f"(s[ni][3])
                    : "r"(a0), "r"(a1), "r"(a2), "r"(a3), "r"(b0), "r"(b1));
            }
        }
        #pragma unroll
        for (int ni = 0; ni < 8; ni++)
            #pragma unroll
            for (int j = 0; j < 4; j++) s[ni][j] *= 0.125f;

        float mx0 = -INFINITY, mx1 = -INFINITY;
        #pragma unroll
        for (int ni = 0; ni < 8; ni++) {
            mx0 = fmaxf(mx0, fmaxf(s[ni][0], s[ni][1]));
            mx1 = fmaxf(mx1, fmaxf(s[ni][2], s[ni][3]));
        }
        mx0 = fmaxf(mx0, __shfl_xor_sync(0xffffffffu, mx0, 1));
        mx0 = fmaxf(mx0, __shfl_xor_sync(0xffffffffu, mx0, 2));
        mx1 = fmaxf(mx1, __shfl_xor_sync(0xffffffffu, mx1, 1));
        mx1 = fmaxf(mx1, __shfl_xor_sync(0xffffffffu, mx1, 2));
        float mn0 = fmaxf(m0r, mx0), mn1 = fmaxf(m1r, mx1);
        float ps0 = 0.f, ps1 = 0.f;
        #pragma unroll
        for (int ni = 0; ni < 8; ni++) {
            s[ni][0] = expf(s[ni][0] - mn0); ps0 += s[ni][0];
            s[ni][1] = expf(s[ni][1] - mn0); ps0 += s[ni][1];
            s[ni][2] = expf(s[ni][2] - mn1); ps1 += s[ni][2];
            s[ni][3] = expf(s[ni][3] - mn1); ps1 += s[ni][3];
        }
        ps0 += __shfl_xor_sync(0xffffffffu, ps0, 1);
        ps0 += __shfl_xor_sync(0xffffffffu, ps0, 2);
        ps1 += __shfl_xor_sync(0xffffffffu, ps1, 1);
        ps1 += __shfl_xor_sync(0xffffffffu, ps1, 2);
        float al0 = expf(m0r - mn0), al1 = expf(m1r - mn1);
        l0 = l0 * al0 + ps0;  m0r = mn0;
        l1 = l1 * al1 + ps1;  m1r = mn1;
        #pragma unroll
        for (int ni = 0; ni < 8; ni++) {
            o[ni][0] *= al0; o[ni][1] *= al0;
            o[ni][2] *= al1; o[ni][3] *= al1;
        }

        __syncthreads();
        #pragma unroll
        for (int ni = 0; ni < 8; ni++) {
            *(float2*)&Ks[rlo*ATS + ni*8 + 2*tc] =
                make_float2(tf32r(s[ni][0]), tf32r(s[ni][1]));
            *(float2*)&Ks[(rlo+8)*ATS + ni*8 + 2*tc] =
                make_float2(tf32r(s[ni][2]), tf32r(s[ni][3]));
        }
        __syncthreads();

        #pragma unroll
        for (int k8 = 0; k8 < 64; k8 += 8) {
            uint32_t a0 = __float_as_uint(Ks[(warp*16 + g)*ATS + k8 + tc]);
            uint32_t a1 = __float_as_uint(Ks[(warp*16 + g + 8)*ATS + k8 + tc]);
            uint32_t a2 = __float_as_uint(Ks[(warp*16 + g)*ATS + k8 + tc + 4]);
            uint32_t a3 = __float_as_uint(Ks[(warp*16 + g + 8)*ATS + k8 + tc + 4]);
            #pragma unroll
            for (int ni = 0; ni < 8; ni++) {
                uint32_t b0 = __float_as_uint(Vs[(k8 + tc)*VTS + ni*8 + g]);
                uint32_t b1 = __float_as_uint(Vs[(k8 + tc + 4)*VTS + ni*8 + g]);
                asm volatile(
                    "mma.sync.aligned.m16n8k8.row.col.f32.tf32.tf32.f32 "
                    "{%0,%1,%2,%3}, {%4,%5,%6,%7}, {%8,%9}, {%0,%1,%2,%3};"
                    : "+f"(o[ni][0]), "+f"(o[ni][1]), "+f"(o[ni][2]), "+f"(o[ni][3])
                    : "r"(a0), "r"(a1), "r"(a2), "r"(a3), "r"(b0), "r"(b1));
            }
        }
    }

    float inv0 = 1.f / l0, inv1 = 1.f / l1;
    #pragma unroll
    for (int ni = 0; ni < 8; ni++) {
        *(float2*)(O + base + (size_t)(q0 + rlo) * Dq + ni*8 + 2*tc) =
            make_float2(tf32r(o[ni][0]*inv0), tf32r(o[ni][1]*inv0));
        *(float2*)(O + base + (size_t)(q0 + rlo + 8) * Dq + ni*8 + 2*tc) =
            make_float2(tf32r(o[ni][2]*inv1), tf32r(o[ni][3]*inv1));
    }
}

// ---------------- host orchestration ----------------
extern "C" void kernel_launch(void* const* d_in, const int* in_sizes, int n_in,
                              void* d_out, int out_size)
{
    (void)n_in; (void)out_size;
    const float* x   = (const float*)d_in[0];
    const float* sn  = (const float*)d_in[1];
    const float* cs  = (const float*)d_in[2];
    const float* w1s[3] = {(const float*)d_in[3], (const float*)d_in[7],  (const float*)d_in[11]};
    const float* b1s[3] = {(const float*)d_in[4], (const float*)d_in[8],  (const float*)d_in[12]};
    const float* w2s[3] = {(const float*)d_in[5], (const float*)d_in[9],  (const float*)d_in[13]};
    const float* b2s[3] = {(const float*)d_in[6], (const float*)d_in[10], (const float*)d_in[14]};
    const float* ln1g = (const float*)d_in[15];
    const float* ln1b = (const float*)d_in[16];
    const float* ln2g = (const float*)d_in[17];
    const float* ln2b = (const float*)d_in[18];

    const float *wq, *bqv, *wk, *bkv, *wv, *bvv, *wo, *bov;
    if (in_sizes[20] == 768) {
        wq = (const float*)d_in[19]; bqv = (const float*)d_in[20];
        wk = (const float*)d_in[21]; bkv = (const float*)d_in[22];
        wv = (const float*)d_in[23]; bvv = (const float*)d_in[24];
        wo = (const float*)d_in[25]; bov = (const float*)d_in[26];
    } else {
        wq = (const float*)d_in[19]; wk  = (const float*)d_in[20];
        wv = (const float*)d_in[21]; wo  = (const float*)d_in[22];
        bqv = (const float*)d_in[23]; bkv = (const float*)d_in[24];
        bvv = (const float*)d_in[25]; bov = (const float*)d_in[26];
    }
    const float* mw1 = (const float*)d_in[27]; const float* mb1 = (const float*)d_in[28];
    const float* mw2 = (const float*)d_in[29]; const float* mb2 = (const float*)d_in[30];

    float *t1, *pp, *ha, *hb, *gx, *gqk, *gq, *gk, *gv, *gatt, *go, *gx2, *wr;
    cudaGetSymbolAddress((void**)&t1,  g_t1);
    cudaGetSymbolAddress((void**)&pp,  g_p);
    cudaGetSymbolAddress((void**)&ha,  g_ha);
    cudaGetSymbolAddress((void**)&hb,  g_hb);
    cudaGetSymbolAddress((void**)&gx,  g_x);
    cudaGetSymbolAddress((void**)&gqk, g_qk);
    cudaGetSymbolAddress((void**)&gq,  g_q);
    cudaGetSymbolAddress((void**)&gk,  g_k);
    cudaGetSymbolAddress((void**)&gv,  g_v);
    cudaGetSymbolAddress((void**)&gatt,g_att);
    cudaGetSymbolAddress((void**)&go,  g_o);
    cudaGetSymbolAddress((void**)&gx2, g_x2);
    cudaGetSymbolAddress((void**)&wr,  g_wr);

    // ---- pre-round all weights (one launch); dst contiguous in g_wr ----
    WSrc ws;
    ws.s[0] = (const float4*)w1s[0]; ws.s[1] = (const float4*)w1s[1];
    ws.s[2] = (const float4*)w1s[2]; ws.s[3] = (const float4*)w2s[0];
    ws.s[4] = (const float4*)w2s[1]; ws.s[5] = (const float4*)w2s[2];
    ws.s[6] = (const float4*)wq;     ws.s[7] = (const float4*)wk;
    ws.s[8] = (const float4*)wv;     ws.s[9] = (const float4*)wo;
    ws.s[10] = (const float4*)mw1;   ws.s[11] = (const float4*)mw2;
    round_all<<<(W_TOTAL4 + 255)/256, 256>>>(ws, (float4*)wr);

    const float* rw1[3] = {wr, wr + 2359296, wr + 4718592};
    const float* rw2[3] = {wr + 7077888, wr + 7120896, wr + 8300544};
    const float *rwq = wr + 11446272, *rwk = wr + 12036096;
    const float *rwv = wr + 12625920, *rwo = wr + 13215744;
    const float *rmw1 = wr + 13805568, *rmw2 = wr + 16164864;

    cudaFuncSetAttribute(gemm_tc<1,0,1,1>, cudaFuncAttributeMaxDynamicSharedMemorySize, GEMM_SMEM);
    cudaFuncSetAttribute(gemm_tc<0,0,0,0>, cudaFuncAttributeMaxDynamicSharedMemorySize, GEMM_SMEM);
    cudaFuncSetAttribute(gemm_tc_sk<0>,    cudaFuncAttributeMaxDynamicSharedMemorySize, GEMM_SMEM);
    cudaFuncSetAttribute(gemm_tc_sk<1>,    cudaFuncAttributeMaxDynamicSharedMemorySize, GEMM_SMEM);
    cudaFuncSetAttribute(gemm_qkv,         cudaFuncAttributeMaxDynamicSharedMemorySize, GEMM_SMEM);
    cudaFuncSetAttribute(conv_tiled<128>,  cudaFuncAttributeMaxDynamicSharedMemorySize, CONV_SMEM);
    cudaFuncSetAttribute(conv_tiled<256>,  cudaFuncAttributeMaxDynamicSharedMemorySize, CONV_SMEM);
    cudaFuncSetAttribute(attn_mma,         cudaFuncAttributeMaxDynamicSharedMemorySize, ATT_SMEM);

    const int orderF[3] = {14, 384, 1024};
    const int Fs[3]     = {7, 128, 256};
    const int ords[3]   = {2, 3, 4};
    const int skS[3]    = {4, 4, 2};      // split-K chunks per stage
    const int skKC[3]   = {768, 768, 1536};

    const float* hcur = x;                 // h starts as x (read-only)
    float* bufs[2] = {ha, hb};
    int cur = 0;
    const int convBlocks = (ROWS * (Dq/4) + 255) / 256;

    for (int s3 = 0; s3 < 3; s3++) {
        gemm_tc<1,0,1,1><<<dim3(24,32), 256, GEMM_SMEM>>>(hcur, rw1[s3], b1s[s3], nullptr, t1, 3072, 768);
        cudaMemsetAsync(pp, 0, sizeof(float)*(size_t)ROWS*orderF[s3]);
        gemm_tc_sk<0><<<dim3((orderF[s3]+127)/128, 32, skS[s3]), 256, GEMM_SMEM>>>(
            t1, rw2[s3], b2s[s3], nullptr, pp, orderF[s3], 3072, skKC[s3]);
        for (int i = 0; i < ords[s3]; i++) {
            if (Fs[s3] == 7)
                conv_gelu<<<convBlocks, 256>>>(hcur, pp, bufs[cur], 7, orderF[s3], i * 7);
            else if (Fs[s3] == 128)
                conv_tiled<128><<<dim3(12,64), 256, CONV_SMEM>>>(hcur, pp, bufs[cur], orderF[s3], i * 128);
            else
                conv_tiled<256><<<dim3(12,64), 256, CONV_SMEM>>>(hcur, pp, bufs[cur], orderF[s3], i * 256);
            hcur = bufs[cur];
            cur ^= 1;
        }
    }

    ln_rope_kernel<<<ROWS, 256>>>(x, hcur, ln1g, ln1b, sn, cs, gx, gqk);

    gemm_qkv<<<dim3(6,32,3), 256, GEMM_SMEM>>>(gqk, gx, rwq, bqv, gq, rwk, bkv, gk, rwv, bvv, gv);

    attn_mma<<<dim3(Lq/64, Bq*Hq), 128, ATT_SMEM>>>(gq, gk, gv, gatt);

    gemm_tc<0,0,0,0><<<dim3(6,32), 256, GEMM_SMEM>>>(gatt, rwo, bov, nullptr, go, 768, 768);
    ln_kernel<<<ROWS, 256>>>(gx, go, ln2g, ln2b, gx2);
    gemm_tc<1,0,1,1><<<dim3(24,32), 256, GEMM_SMEM>>>(gx2, rmw1, mb1, nullptr, t1, 3072, 768);
    cudaMemsetAsync(d_out, 0, sizeof(float)*(size_t)ROWS*768);
    gemm_tc_sk<1><<<dim3(6,32,2), 256, GEMM_SMEM>>>(
        t1, rmw2, mb2, gx2, (float*)d_out, 768, 3072, 1536);
}

// round 9
// speedup vs baseline: 5.0328x; 1.0388x over previous
#include <cuda_runtime.h>
#include <math.h>
#include <stdint.h>

#define Bq 2
#define Lq 2048
#define Dq 768
#define Hq 12
#define ROWS (Bq*Lq)   /* 4096 */

// ---------------- scratch (device globals; no allocation allowed) ----------------
__device__ float g_t1[(size_t)ROWS*3072];
__device__ float g_p [(size_t)ROWS*1024];
__device__ float g_ha[(size_t)ROWS*Dq];
__device__ float g_hb[(size_t)ROWS*Dq];
__device__ float g_x [(size_t)ROWS*Dq];
__device__ float g_qk[(size_t)ROWS*Dq];
__device__ float g_q [(size_t)ROWS*Dq];
__device__ float g_k [(size_t)ROWS*Dq];
__device__ float g_v [(size_t)ROWS*Dq];
__device__ float g_att[(size_t)ROWS*Dq];
__device__ float g_o [(size_t)ROWS*Dq];
__device__ float g_x2[(size_t)ROWS*Dq];
__device__ float g_wr[18524160];   // pre-rounded weights (74MB), contiguous

__device__ __forceinline__ float gelu_f(float x){
    return 0.5f*x*(1.0f+erff(x*0.70710678118654752440f));
}
__device__ __forceinline__ uint32_t tf32u(float x){
    uint32_t u;
    asm("cvt.rna.tf32.f32 %0, %1;" : "=r"(u) : "f"(x));
    return u;
}
__device__ __forceinline__ float tf32r(float x){
    return __uint_as_float(tf32u(x));
}
__device__ __forceinline__ void cp16(uint32_t smem_dst, const void* gsrc){
    asm volatile("cp.async.ca.shared.global [%0], [%1], 16;\n"
                 :: "r"(smem_dst), "l"(gsrc));
}

// ---------------- merged tf32 round-copy of all 12 weight matrices ----------------
struct WSrc { const float4* s[12]; };
#define W_TOTAL4 4631040
__global__ void round_all(WSrc w, float4* __restrict__ dst)
{
    const int end4[12] = {589824, 1179648, 1769472, 1780224, 2075136, 2861568,
                          3009024, 3156480, 3303936, 3451392, 4041216, 4631040};
    int i = blockIdx.x * blockDim.x + threadIdx.x;
    if (i >= W_TOTAL4) return;
    int s = 0;
    #pragma unroll
    for (int k = 0; k < 12; k++) if (i >= end4[k]) s = k + 1;
    int st = (s == 0) ? 0 : end4[s-1];
    float4 v = w.s[s][i - st];
    dst[i] = make_float4(tf32r(v.x), tf32r(v.y), tf32r(v.z), tf32r(v.w));
}

// ---------------- tensor-core TF32 GEMM body, 2-stage cp.async pipeline
#define GEMM_SMEM (2*(128*36 + 32*136)*4)
template<int GELU, int RES, int CVTA, int ROUT>
__device__ __forceinline__ void gemm_body(
    const float* __restrict__ A, const float* __restrict__ Bm,
    const float* __restrict__ bias, const float* __restrict__ Rr,
    float* __restrict__ C, int N, int K)
{
    extern __shared__ uint32_t smem_u[];
    uint32_t* AsB = smem_u;
    uint32_t* BsB = smem_u + 2*128*36;
    const int tid  = threadIdx.x;
    const int warp = tid >> 5, lane = tid & 31;
    const int g = lane >> 2, tc = lane & 3;
    const int wm0 = (warp & 1) * 64, wn0 = (warp >> 1) * 32;
    const int row0 = blockIdx.y * 128, col0 = blockIdx.x * 128;
    const bool colFull = (col0 + 128 <= N);

    float acc[4][4][4] = {};
    const int ar = tid >> 3,  ac = (tid & 7) * 4;
    const int bk = tid >> 5,  bc = (tid & 31) * 4;
    const int nt = K / 32;

    auto issue = [&](int kt, int s){
        uint32_t* as = AsB + s * (128*36);
        uint32_t* bs = BsB + s * (32*136);
        const int k0 = kt * 32;
        #pragma unroll
        for (int p = 0; p < 4; p++) {
            int r = ar + p * 32;
            cp16((uint32_t)__cvta_generic_to_shared(&as[r*36 + ac]),
                 A + (size_t)(row0 + r) * K + k0 + ac);
        }
        if (colFull) {
            #pragma unroll
            for (int p = 0; p < 4; p++) {
                int kr = bk + p * 8;
                cp16((uint32_t)__cvta_generic_to_shared(&bs[kr*136 + bc]),
                     Bm + (size_t)(k0 + kr) * N + col0 + bc);
            }
        } else {
            #pragma unroll
            for (int p = 0; p < 4; p++) {
                int kr = bk + p * 8;
                #pragma unroll
                for (int u = 0; u < 4; u++) {
                    int c = col0 + bc + u;
                    bs[kr*136 + bc + u] =
                        (c < N) ? __float_as_uint(Bm[(size_t)(k0 + kr) * N + c]) : 0u;
                }
            }
        }
        asm volatile("cp.async.commit_group;\n");
    };

    issue(0, 0);
    for (int kt = 0; kt < nt; kt++) {
        const int cur = kt & 1;
        if (kt + 1 < nt) {
            issue(kt + 1, cur ^ 1);
            asm volatile("cp.async.wait_group 1;\n");
        } else {
            asm volatile("cp.async.wait_group 0;\n");
        }
        __syncthreads();
        const uint32_t* as = AsB + cur * (128*36);
        const uint32_t* bs = BsB + cur * (32*136);
        #pragma unroll
        for (int k8 = 0; k8 < 32; k8 += 8) {
            uint32_t af[4][4], bf[4][2];
            #pragma unroll
            for (int mi = 0; mi < 4; mi++) {
                const uint32_t* base = &as[(wm0 + mi*16 + g) * 36 + k8 + tc];
                if (CVTA) {
                    af[mi][0] = tf32u(__uint_as_float(base[0]));
                    af[mi][1] = tf32u(__uint_as_float(base[8*36]));
                    af[mi][2] = tf32u(__uint_as_float(base[4]));
                    af[mi][3] = tf32u(__uint_as_float(base[8*36 + 4]));
                } else {
                    af[mi][0] = base[0];
                    af[mi][1] = base[8*36];
                    af[mi][2] = base[4];
                    af[mi][3] = base[8*36 + 4];
                }
            }
            #pragma unroll
            for (int ni = 0; ni < 4; ni++) {
                const uint32_t* base = &bs[(k8 + tc) * 136 + wn0 + ni*8 + g];
                bf[ni][0] = base[0];
                bf[ni][1] = base[4*136];
            }
            #pragma unroll
            for (int mi = 0; mi < 4; mi++)
                #pragma unroll
                for (int ni = 0; ni < 4; ni++)
                    asm volatile(
                        "mma.sync.aligned.m16n8k8.row.col.f32.tf32.tf32.f32 "
                        "{%0,%1,%2,%3}, {%4,%5,%6,%7}, {%8,%9}, {%0,%1,%2,%3};"
                        : "+f"(acc[mi][ni][0]), "+f"(acc[mi][ni][1]),
                          "+f"(acc[mi][ni][2]), "+f"(acc[mi][ni][3])
                        : "r"(af[mi][0]), "r"(af[mi][1]), "r"(af[mi][2]), "r"(af[mi][3]),
                          "r"(bf[ni][0]), "r"(bf[ni][1]));
        }
        __syncthreads();
    }

    #pragma unroll
    for (int mi = 0; mi < 4; mi++) {
        int r0 = row0 + wm0 + mi*16 + g;
        #pragma unroll
        for (int ni = 0; ni < 4; ni++) {
            int c = col0 + wn0 + ni*8 + tc*2;
            if (c < N) {
                float b0 = bias[c], b1 = bias[c+1];
                float v0 = acc[mi][ni][0] + b0, v1 = acc[mi][ni][1] + b1;
                float v2 = acc[mi][ni][2] + b0, v3 = acc[mi][ni][3] + b1;
                if (GELU) { v0 = gelu_f(v0); v1 = gelu_f(v1); v2 = gelu_f(v2); v3 = gelu_f(v3); }
                if (ROUT) { v0 = tf32r(v0); v1 = tf32r(v1); v2 = tf32r(v2); v3 = tf32r(v3); }
                if (RES) {
                    v0 += Rr[(size_t)r0*N + c];     v1 += Rr[(size_t)r0*N + c + 1];
                    v2 += Rr[(size_t)(r0+8)*N + c]; v3 += Rr[(size_t)(r0+8)*N + c + 1];
                }
                *(float2*)(C + (size_t)r0*N + c)     = make_float2(v0, v1);
                *(float2*)(C + (size_t)(r0+8)*N + c) = make_float2(v2, v3);
            }
        }
    }
}

template<int GELU, int RES, int CVTA, int ROUT>
__global__ void __launch_bounds__(256, 2) gemm_tc(
    const float* __restrict__ A, const float* __restrict__ Bm,
    const float* __restrict__ bias, const float* __restrict__ Rr,
    float* __restrict__ C, int N, int K)
{
    gemm_body<GELU, RES, CVTA, ROUT>(A, Bm, bias, Rr, C, N, K);
}

// ---------------- split-K TF32 GEMM: C += chunk via atomicAdd (C pre-zeroed)
template<int RES>
__global__ void __launch_bounds__(256, 2) gemm_tc_sk(
    const float* __restrict__ A, const float* __restrict__ Bm,
    const float* __restrict__ bias, const float* __restrict__ Rr,
    float* __restrict__ C, int N, int K, int KC)
{
    extern __shared__ uint32_t smem_u[];
    uint32_t* AsB = smem_u;
    uint32_t* BsB = smem_u + 2*128*36;
    const int tid  = threadIdx.x;
    const int warp = tid >> 5, lane = tid & 31;
    const int g = lane >> 2, tc = lane & 3;
    const int wm0 = (warp & 1) * 64, wn0 = (warp >> 1) * 32;
    const int row0 = blockIdx.y * 128, col0 = blockIdx.x * 128;
    const int z = blockIdx.z;
    const int kbase = z * KC;
    const bool colFull = (col0 + 128 <= N);

    float acc[4][4][4] = {};
    const int ar = tid >> 3,  ac = (tid & 7) * 4;
    const int bk = tid >> 5,  bc = (tid & 31) * 4;
    const int nt = KC / 32;

    auto issue = [&](int kt, int s){
        uint32_t* as = AsB + s * (128*36);
        uint32_t* bs = BsB + s * (32*136);
        const int k0 = kbase + kt * 32;
        #pragma unroll
        for (int p = 0; p < 4; p++) {
            int r = ar + p * 32;
            cp16((uint32_t)__cvta_generic_to_shared(&as[r*36 + ac]),
                 A + (size_t)(row0 + r) * K + k0 + ac);
        }
        if (colFull) {
            #pragma unroll
            for (int p = 0; p < 4; p++) {
                int kr = bk + p * 8;
                cp16((uint32_t)__cvta_generic_to_shared(&bs[kr*136 + bc]),
                     Bm + (size_t)(k0 + kr) * N + col0 + bc);
            }
        } else {
            #pragma unroll
            for (int p = 0; p < 4; p++) {
                int kr = bk + p * 8;
                #pragma unroll
                for (int u = 0; u < 4; u++) {
                    int c = col0 + bc + u;
                    bs[kr*136 + bc + u] =
                        (c < N) ? __float_as_uint(Bm[(size_t)(k0 + kr) * N + c]) : 0u;
                }
            }
        }
        asm volatile("cp.async.commit_group;\n");
    };

    issue(0, 0);
    for (int kt = 0; kt < nt; kt++) {
        const int cur = kt & 1;
        if (kt + 1 < nt) {
            issue(kt + 1, cur ^ 1);
            asm volatile("cp.async.wait_group 1;\n");
        } else {
            asm volatile("cp.async.wait_group 0;\n");
        }
        __syncthreads();
        const uint32_t* as = AsB + cur * (128*36);
        const uint32_t* bs = BsB + cur * (32*136);
        #pragma unroll
        for (int k8 = 0; k8 < 32; k8 += 8) {
            uint32_t af[4][4], bf[4][2];
            #pragma unroll
            for (int mi = 0; mi < 4; mi++) {
                const uint32_t* base = &as[(wm0 + mi*16 + g) * 36 + k8 + tc];
                af[mi][0] = base[0];
                af[mi][1] = base[8*36];
                af[mi][2] = base[4];
                af[mi][3] = base[8*36 + 4];
            }
            #pragma unroll
            for (int ni = 0; ni < 4; ni++) {
                const uint32_t* base = &bs[(k8 + tc) * 136 + wn0 + ni*8 + g];
                bf[ni][0] = base[0];
                bf[ni][1] = base[4*136];
            }
            #pragma unroll
            for (int mi = 0; mi < 4; mi++)
                #pragma unroll
                for (int ni = 0; ni < 4; ni++)
                    asm volatile(
                        "mma.sync.aligned.m16n8k8.row.col.f32.tf32.tf32.f32 "
                        "{%0,%1,%2,%3}, {%4,%5,%6,%7}, {%8,%9}, {%0,%1,%2,%3};"
                        : "+f"(acc[mi][ni][0]), "+f"(acc[mi][ni][1]),
                          "+f"(acc[mi][ni][2]), "+f"(acc[mi][ni][3])
                        : "r"(af[mi][0]), "r"(af[mi][1]), "r"(af[mi][2]), "r"(af[mi][3]),
                          "r"(bf[ni][0]), "r"(bf[ni][1]));
        }
        __syncthreads();
    }

    const bool lead = (z == 0);
    #pragma unroll
    for (int mi = 0; mi < 4; mi++) {
        int r0 = row0 + wm0 + mi*16 + g;
        #pragma unroll
        for (int ni = 0; ni < 4; ni++) {
            int c = col0 + wn0 + ni*8 + tc*2;
            if (c < N) {
                float v0 = acc[mi][ni][0], v1 = acc[mi][ni][1];
                float v2 = acc[mi][ni][2], v3 = acc[mi][ni][3];
                if (lead) {
                    float b0 = bias[c], b1 = bias[c+1];
                    v0 += b0; v1 += b1; v2 += b0; v3 += b1;
                    if (RES) {
                        v0 += Rr[(size_t)r0*N + c];     v1 += Rr[(size_t)r0*N + c + 1];
                        v2 += Rr[(size_t)(r0+8)*N + c]; v3 += Rr[(size_t)(r0+8)*N + c + 1];
                    }
                }
                atomicAdd(C + (size_t)r0*N + c,       v0);
                atomicAdd(C + (size_t)r0*N + c + 1,   v1);
                atomicAdd(C + (size_t)(r0+8)*N + c,   v2);
                atomicAdd(C + (size_t)(r0+8)*N + c+1, v3);
            }
        }
    }
}

// fused q/k/v projection
__global__ void __launch_bounds__(256, 2) gemm_qkv(
    const float* __restrict__ gqk, const float* __restrict__ gx,
    const float* __restrict__ wq, const float* __restrict__ bq, float* __restrict__ oq,
    const float* __restrict__ wk, const float* __restrict__ bk, float* __restrict__ ok,
    const float* __restrict__ wv, const float* __restrict__ bv, float* __restrict__ ov)
{
    const int z = blockIdx.z;
    if (z == 2) {
        gemm_body<0,0,1,1>(gx, wv, bv, nullptr, ov, 768, 768);
    } else if (z == 1) {
        gemm_body<0,0,0,1>(gqk, wk, bk, nullptr, ok, 768, 768);
    } else {
        gemm_body<0,0,0,1>(gqk, wq, bq, nullptr, oq, 768, 768);
    }
}

// ---------------- direct conv (F=7 only) + GELU
__global__ void conv_gelu(const float* __restrict__ h, const float* __restrict__ p,
                          float* __restrict__ out, int F, int pstride, int poff)
{
    int idx = blockIdx.x * blockDim.x + threadIdx.x;
    if (idx >= ROWS * (Dq/4)) return;
    int d4 = idx % (Dq/4);
    int bt = idx / (Dq/4);
    int t  = bt & (Lq - 1);
    const float* kr = p + (size_t)bt * pstride + poff;
    int mmax = min(F - 1, t);
    float ax = 0.f, ay = 0.f, az = 0.f, aw = 0.f;
    for (int m = mmax; m >= 0; --m) {
        float kv = __ldg(kr + m);
        const float4 hv = *(const float4*)(h + (size_t)(bt - m) * Dq + d4 * 4);
        ax = fmaf(kv, hv.x, ax);
        ay = fmaf(kv, hv.y, ay);
        az = fmaf(kv, hv.z, az);
        aw = fmaf(kv, hv.w, aw);
    }
    float4 o;
    o.x = gelu_f(ax); o.y = gelu_f(ay); o.z = gelu_f(az); o.w = gelu_f(aw);
    *(float4*)(out + (size_t)bt * Dq + d4 * 4) = o;
}

// ---------------- smem-tiled conv + GELU, register sliding window (F in {128,256})
#define CONV_SMEM ((128*68 + 64*68)*4)
template<int F>
__global__ void __launch_bounds__(256) conv_tiled(
    const float* __restrict__ h, const float* __restrict__ p,
    float* __restrict__ out, int pstride, int poff)
{
    extern __shared__ float csm[];
    float* hs = csm;            // 128 x 68
    float* ps = csm + 128*68;   // 64 x 68
    const int tid = threadIdx.x;
    const int d0  = blockIdx.x * 64;
    const int bt0 = blockIdx.y * 64;
    const int batch = bt0 / Lq;
    const int t0    = bt0 & (Lq - 1);
    const int tg = tid >> 4;
    const int dg = tid & 15;

    float4 acc[4];
    #pragma unroll
    for (int i = 0; i < 4; i++) acc[i] = make_float4(0.f, 0.f, 0.f, 0.f);

    for (int m0 = F - 64; m0 >= 0; m0 -= 64) {
        if (m0 != F - 64) __syncthreads();   // prior reads done before overwrite
        for (int idx = tid; idx < 128*16; idx += 256) {
            int row = idx >> 4, c4 = (idx & 15) * 4;
            int lt = t0 - m0 - 64 + row;
            float4 v = make_float4(0.f, 0.f, 0.f, 0.f);
            if (lt >= 0)
                v = *(const float4*)(h + (size_t)(batch*Lq + lt) * Dq + d0 + c4);
            *(float4*)&hs[row*68 + c4] = v;
        }
        for (int idx = tid; idx < 64*16; idx += 256) {
            int row = idx >> 4, c4 = (idx & 15) * 4;
            float4 v = *(const float4*)(p + (size_t)(bt0 + row) * pstride + poff + m0 + c4);
            *(float4*)&ps[row*68 + c4] = v;
        }
        __syncthreads();

        // sliding register window: at tap mi, thread needs hs rows (tg*4+64-mi)+i
        float4 win[4];
        #pragma unroll
        for (int j = 0; j < 4; j++)
            win[j] = *(const float4*)&hs[(tg*4 + 1 + j)*68 + dg*4];

        #pragma unroll
        for (int grp = 15; grp >= 0; --grp) {
            float pka[4][4];
            #pragma unroll
            for (int i = 0; i < 4; i++)
                *(float4*)pka[i] = *(const float4*)&ps[(tg*4 + i)*68 + grp*4];
            #pragma unroll
            for (int u = 3; u >= 0; --u) {
                const int mi = grp*4 + u;
                #pragma unroll
                for (int i = 0; i < 4; i++) {
                    float pk = pka[i][u];
                    acc[i].x = fmaf(pk, win[i].x, acc[i].x);
                    acc[i].y = fmaf(pk, win[i].y, acc[i].y);
                    acc[i].z = fmaf(pk, win[i].z, acc[i].z);
                    acc[i].w = fmaf(pk, win[i].w, acc[i].w);
                }
                if (mi > 0) {
                    win[0] = win[1]; win[1] = win[2]; win[2] = win[3];
                    win[3] = *(const float4*)&hs[(tg*4 + 68 - mi)*68 + dg*4];
                }
            }
        }
    }

    #pragma unroll
    for (int i = 0; i < 4; i++) {
        float4 o;
        o.x = gelu_f(acc[i].x); o.y = gelu_f(acc[i].y);
        o.z = gelu_f(acc[i].z); o.w = gelu_f(acc[i].w);
        *(float4*)(out + (size_t)(bt0 + tg*4 + i) * Dq + d0 + dg*4) = o;
    }
}

// ---------------- LayerNorm of (a+b): two-pass, fp64 accumulators
__global__ void ln_kernel(const float* __restrict__ a, const float* __restrict__ b,
                          const float* __restrict__ g, const float* __restrict__ be,
                          float* __restrict__ out)
{
    __shared__ double red[10];
    int row = blockIdx.x, tid = threadIdx.x;
    const float* pa = a + (size_t)row * Dq;
    const float* pb = b + (size_t)row * Dq;
    float v[3];
    double s = 0.0;
    #pragma unroll
    for (int i = 0; i < 3; i++) {
        float x = pa[tid + 256*i] + pb[tid + 256*i];
        v[i] = x; s += (double)x;
    }
    #pragma unroll
    for (int o = 16; o; o >>= 1) s += __shfl_down_sync(0xffffffffu, s, o);
    if ((tid & 31) == 0) red[tid >> 5] = s;
    __syncthreads();
    if (tid == 0) {
        double t = 0.0;
        #pragma unroll
        for (int w = 0; w < 8; w++) t += red[w];
        red[8] = t * (1.0/768.0);
    }
    __syncthreads();
    float mean = (float)red[8];

    double s2 = 0.0;
    #pragma unroll
    for (int i = 0; i < 3; i++) {
        double d = (double)v[i] - red[8];
        s2 += d * d;
    }
    #pragma unroll
    for (int o = 16; o; o >>= 1) s2 += __shfl_down_sync(0xffffffffu, s2, o);
    if ((tid & 31) == 0) red[tid >> 5] = s2;
    __syncthreads();
    if (tid == 0) {
        double t = 0.0;
        #pragma unroll
        for (int w = 0; w < 8; w++) t += red[w];
        red[9] = 1.0 / sqrt(t * (1.0/768.0) + 1e-5);
    }
    __syncthreads();
    float rs = (float)red[9];
    #pragma unroll
    for (int i = 0; i < 3; i++) {
        int c = tid + 256*i;
        out[(size_t)row * Dq + c] = (v[i] - mean) * rs * g[c] + be[c];
    }
}

// ---------------- fused LayerNorm(a+b) + RoPE
__global__ void ln_rope_kernel(const float* __restrict__ a, const float* __restrict__ b,
                               const float* __restrict__ g, const float* __restrict__ be,
                               const float* __restrict__ sn, const float* __restrict__ cs,
                               float* __restrict__ ox, float* __restrict__ oqk)
{
    __shared__ double red[10];
    __shared__ float srow[768];
    int row = blockIdx.x, tid = threadIdx.x;
    int l = row & (Lq - 1);
    const float* pa = a + (size_t)row * Dq;
    const float* pb = b + (size_t)row * Dq;
    float v[3];
    double s = 0.0;
    #pragma unroll
    for (int i = 0; i < 3; i++) {
        float x = pa[tid + 256*i] + pb[tid + 256*i];
        v[i] = x; s += (double)x;
    }
    #pragma unroll
    for (int o = 16; o; o >>= 1) s += __shfl_down_sync(0xffffffffu, s, o);
    if ((tid & 31) == 0) red[tid >> 5] = s;
    __syncthreads();
    if (tid == 0) {
        double t = 0.0;
        #pragma unroll
        for (int w = 0; w < 8; w++) t += red[w];
        red[8] = t * (1.0/768.0);
    }
    __syncthreads();
    float mean = (float)red[8];

    double s2 = 0.0;
    #pragma unroll
    for (int i = 0; i < 3; i++) {
        double d = (double)v[i] - red[8];
        s2 += d * d;
    }
    #pragma unroll
    for (int o = 16; o; o >>= 1) s2 += __shfl_down_sync(0xffffffffu, s2, o);
    if ((tid & 31) == 0) red[tid >> 5] = s2;
    __syncthreads();
    if (tid == 0) {
        double t = 0.0;
        #pragma unroll
        for (int w = 0; w < 8; w++) t += red[w];
        red[9] = 1.0 / sqrt(t * (1.0/768.0) + 1e-5);
    }
    __syncthreads();
    float rs = (float)red[9];
    #pragma unroll
    for (int i = 0; i < 3; i++) {
        int c = tid + 256*i;
        float y = (v[i] - mean) * rs * g[c] + be[c];
        ox[(size_t)row * Dq + c] = y;
        srow[c] = y;
    }
    __syncthreads();
    #pragma unroll
    for (int i = 0; i < 3; i++) {
        int c = tid + 256*i;
        float r;
        if (c < 384) {
            float sv = sn[l*384 + c], cv = cs[l*384 + c];
            r = srow[c] * cv - srow[c + 384] * sv;
        } else {
            int d = c - 384;
            float sv = sn[l*384 + d], cv = cs[l*384 + d];
            r = srow[c] * cv + srow[d] * sv;
        }
        oqk[(size_t)row * Dq + c] = tf32r(r);
    }
}

// ---------------- tensor-core flash attention, hd=64
#define ATS 68
#define VTS 72
#define PS  68
#define ATT_SMEM ((2*64*ATS + 64*VTS + 64*PS)*4)
__global__ void __launch_bounds__(128) attn_mma(
    const float* __restrict__ Q, const float* __restrict__ K,
    const float* __restrict__ V, float* __restrict__ O)
{
    extern __shared__ float sm[];
    float* Qs = sm;
    float* Ks = sm + 64*ATS;
    float* Vs = sm + 2*64*ATS;
    float* Ps = sm + 2*64*ATS + 64*VTS;
    const int tid = threadIdx.x;
    const int warp = tid >> 5, lane = tid & 31;
    const int g = lane >> 2, tc = lane & 3;
    const int bh = blockIdx.y;
    const int b = bh / Hq, h = bh % Hq;
    const int q0 = blockIdx.x * 64;
    const size_t base = (size_t)b * Lq * Dq + (size_t)h * 64;
    const int rlo = warp*16 + g;

    for (int i = tid; i < 64*16; i += 128) {
        int rr = i >> 4, c4 = (i & 15) * 4;
        *(float4*)&Qs[rr*ATS + c4] = *(const float4*)(Q + base + (size_t)(q0 + rr) * Dq + c4);
    }

    float m0r = -INFINITY, m1r = -INFINITY, l0 = 0.f, l1 = 0.f;
    float o[8][4];
    #pragma unroll
    for (int ni = 0; ni < 8; ni++)
        #pragma unroll
        for (int j = 0; j < 4; j++) o[ni][j] = 0.f;

    for (int kt = 0; kt < Lq/64; ++kt) {
        __syncthreads();
        for (int i = tid; i < 64*16; i += 128) {
            int rr = i >> 4, c4 = (i & 15) * 4;
            *(float4*)&Ks[rr*ATS + c4] = *(const float4*)(K + base + (size_t)(kt*64 + rr) * Dq + c4);
            *(float4*)&Vs[rr*VTS + c4] = *(const float4*)(V + base + (size_t)(kt*64 + rr) * Dq + c4);
        }
        __syncthreads();

        float s[8][4];
        #pragma unroll
        for (int ni = 0; ni < 8; ni++)
            #pragma unroll
            for (int j = 0; j < 4; j++) s[ni][j] = 0.f;
        #pragma unroll
        for (int k8 = 0; k8 < 64; k8 += 8) {
            uint32_t a0 = __float_as_uint(Qs[(warp*16 + g)*ATS + k8 + tc]);
            uint32_t a1 = __float_as_uint(Qs[(warp*16 + g + 8)*ATS + k8 + tc]);
            uint32_t a2 = __float_as_uint(Qs[(warp*16 + g)*ATS + k8 + tc + 4]);
            uint32_t a3 = __float_as_uint(Qs[(warp*16 + g + 8)*ATS + k8 + tc + 4]);
            #pragma unroll
            for (int ni = 0; ni < 8; ni++) {
                uint32_t b0 = __float_as_uint(Ks[(ni*8 + g)*ATS + k8 + tc]);
                uint32_t b1 = __float_as_uint(Ks[(ni*8 + g)*ATS + k8 + tc + 4]);
                asm volatile(
                    "mma.sync.aligned.m16n8k8.row.col.f32.tf32.tf32.f32 "
                    "{%0,%1,%2,%3}, {%4,%5,%6,%7}, {%8,%9}, {%0,%1,%2,%3};"
                    : "+f"(s[ni][0]), "+f"(s[ni][1]), "+f"(s[ni][2]), "+f"(s[ni][3])
                    : "r"(a0), "r"(a1), "r"(a2), "r"(a3), "r"(b0), "r"(b1));
            }
        }
        #pragma unroll
        for (int ni = 0; ni < 8; ni++)
            #pragma unroll
            for (int j = 0; j < 4; j++) s[ni][j] *= 0.125f;

        float mx0 = -INFINITY, mx1 = -INFINITY;
        #pragma unroll
        for (int ni = 0; ni < 8; ni++) {
            mx0 = fmaxf(mx0, fmaxf(s[ni][0], s[ni][1]));
            mx1 = fmaxf(mx1, fmaxf(s[ni][2], s[ni][3]));
        }
        mx0 = fmaxf(mx0, __shfl_xor_sync(0xffffffffu, mx0, 1));
        mx0 = fmaxf(mx0, __shfl_xor_sync(0xffffffffu, mx0, 2));
        mx1 = fmaxf(mx1, __shfl_xor_sync(0xffffffffu, mx1, 1));
        mx1 = fmaxf(mx1, __shfl_xor_sync(0xffffffffu, mx1, 2));
        float mn0 = fmaxf(m0r, mx0), mn1 = fmaxf(m1r, mx1);
        float ps0 = 0.f, ps1 = 0.f;
        #pragma unroll
        for (int ni = 0; ni < 8; ni++) {
            s[ni][0] = __expf(s[ni][0] - mn0); ps0 += s[ni][0];
            s[ni][1] = __expf(s[ni][1] - mn0); ps0 += s[ni][1];
            s[ni][2] = __expf(s[ni][2] - mn1); ps1 += s[ni][2];
            s[ni][3] = __expf(s[ni][3] - mn1); ps1 += s[ni][3];
        }
        ps0 += __shfl_xor_sync(0xffffffffu, ps0, 1);
        ps0 += __shfl_xor_sync(0xffffffffu, ps0, 2);
        ps1 += __shfl_xor_sync(0xffffffffu, ps1, 1);
        ps1 += __shfl_xor_sync(0xffffffffu, ps1, 2);
        float al0 = __expf(m0r - mn0), al1 = __expf(m1r - mn1);
        l0 = l0 * al0 + ps0;  m0r = mn0;
        l1 = l1 * al1 + ps1;  m1r = mn1;
        #pragma unroll
        for (int ni = 0; ni < 8; ni++) {
            o[ni][0] *= al0; o[ni][1] *= al0;
            o[ni][2] *= al1; o[ni][3] *= al1;
        }

        // P rows are private per warp (stage 2 reads only own 16 rows):
        // warp-local smem roundtrip, no block sync needed.
        #pragma unroll
        for (int ni = 0; ni < 8; ni++) {
            *(float2*)&Ps[rlo*PS + ni*8 + 2*tc] =
                make_float2(tf32r(s[ni][0]), tf32r(s[ni][1]));
            *(float2*)&Ps[(rlo+8)*PS + ni*8 + 2*tc] =
                make_float2(tf32r(s[ni][2]), tf32r(s[ni][3]));
        }
        __syncwarp();

        #pragma unroll
        for (int k8 = 0; k8 < 64; k8 += 8) {
            uint32_t a0 = __float_as_uint(Ps[(warp*16 + g)*PS + k8 + tc]);
            uint32_t a1 = __float_as_uint(Ps[(warp*16 + g + 8)*PS + k8 + tc]);
            uint32_t a2 = __float_as_uint(Ps[(warp*16 + g)*PS + k8 + tc + 4]);
            uint32_t a3 = __float_as_uint(Ps[(warp*16 + g + 8)*PS + k8 + tc + 4]);
            #pragma unroll
            for (int ni = 0; ni < 8; ni++) {
                uint32_t b0 = __float_as_uint(Vs[(k8 + tc)*VTS + ni*8 + g]);
                uint32_t b1 = __float_as_uint(Vs[(k8 + tc + 4)*VTS + ni*8 + g]);
                asm volatile(
                    "mma.sync.aligned.m16n8k8.row.col.f32.tf32.tf32.f32 "
                    "{%0,%1,%2,%3}, {%4,%5,%6,%7}, {%8,%9}, {%0,%1,%2,%3};"
                    : "+f"(o[ni][0]), "+f"(o[ni][1]), "+f"(o[ni][2]), "+f"(o[ni][3])
                    : "r"(a0), "r"(a1), "r"(a2), "r"(a3), "r"(b0), "r"(b1));
            }
        }
    }

    float inv0 = 1.f / l0, inv1 = 1.f / l1;
    #pragma unroll
    for (int ni = 0; ni < 8; ni++) {
        *(float2*)(O + base + (size_t)(q0 + rlo) * Dq + ni*8 + 2*tc) =
            make_float2(tf32r(o[ni][0]*inv0), tf32r(o[ni][1]*inv0));
        *(float2*)(O + base + (size_t)(q0 + rlo + 8) * Dq + ni*8 + 2*tc) =
            make_float2(tf32r(o[ni][2]*inv1), tf32r(o[ni][3]*inv1));
    }
}

// ---------------- host orchestration ----------------
extern "C" void kernel_launch(void* const* d_in, const int* in_sizes, int n_in,
                              void* d_out, int out_size)
{
    (void)n_in; (void)out_size;
    const float* x   = (const float*)d_in[0];
    const float* sn  = (const float*)d_in[1];
    const float* cs  = (const float*)d_in[2];
    const float* w1s[3] = {(const float*)d_in[3], (const float*)d_in[7],  (const float*)d_in[11]};
    const float* b1s[3] = {(const float*)d_in[4], (const float*)d_in[8],  (const float*)d_in[12]};
    const float* w2s[3] = {(const float*)d_in[5], (const float*)d_in[9],  (const float*)d_in[13]};
    const float* b2s[3] = {(const float*)d_in[6], (const float*)d_in[10], (const float*)d_in[14]};
    const float* ln1g = (const float*)d_in[15];
    const float* ln1b = (const float*)d_in[16];
    const float* ln2g = (const float*)d_in[17];
    const float* ln2b = (const float*)d_in[18];

    const float *wq, *bqv, *wk, *bkv, *wv, *bvv, *wo, *bov;
    if (in_sizes[20] == 768) {
        wq = (const float*)d_in[19]; bqv = (const float*)d_in[20];
        wk = (const float*)d_in[21]; bkv = (const float*)d_in[22];
        wv = (const float*)d_in[23]; bvv = (const float*)d_in[24];
        wo = (const float*)d_in[25]; bov = (const float*)d_in[26];
    } else {
        wq = (const float*)d_in[19]; wk  = (const float*)d_in[20];
        wv = (const float*)d_in[21]; wo  = (const float*)d_in[22];
        bqv = (const float*)d_in[23]; bkv = (const float*)d_in[24];
        bvv = (const float*)d_in[25]; bov = (const float*)d_in[26];
    }
    const float* mw1 = (const float*)d_in[27]; const float* mb1 = (const float*)d_in[28];
    const float* mw2 = (const float*)d_in[29]; const float* mb2 = (const float*)d_in[30];

    float *t1, *pp, *ha, *hb, *gx, *gqk, *gq, *gk, *gv, *gatt, *go, *gx2, *wr;
    cudaGetSymbolAddress((void**)&t1,  g_t1);
    cudaGetSymbolAddress((void**)&pp,  g_p);
    cudaGetSymbolAddress((void**)&ha,  g_ha);
    cudaGetSymbolAddress((void**)&hb,  g_hb);
    cudaGetSymbolAddress((void**)&gx,  g_x);
    cudaGetSymbolAddress((void**)&gqk, g_qk);
    cudaGetSymbolAddress((void**)&gq,  g_q);
    cudaGetSymbolAddress((void**)&gk,  g_k);
    cudaGetSymbolAddress((void**)&gv,  g_v);
    cudaGetSymbolAddress((void**)&gatt,g_att);
    cudaGetSymbolAddress((void**)&go,  g_o);
    cudaGetSymbolAddress((void**)&gx2, g_x2);
    cudaGetSymbolAddress((void**)&wr,  g_wr);

    WSrc ws;
    ws.s[0] = (const float4*)w1s[0]; ws.s[1] = (const float4*)w1s[1];
    ws.s[2] = (const float4*)w1s[2]; ws.s[3] = (const float4*)w2s[0];
    ws.s[4] = (const float4*)w2s[1]; ws.s[5] = (const float4*)w2s[2];
    ws.s[6] = (const float4*)wq;     ws.s[7] = (const float4*)wk;
    ws.s[8] = (const float4*)wv;     ws.s[9] = (const float4*)wo;
    ws.s[10] = (const float4*)mw1;   ws.s[11] = (const float4*)mw2;
    round_all<<<(W_TOTAL4 + 255)/256, 256>>>(ws, (float4*)wr);

    const float* rw1[3] = {wr, wr + 2359296, wr + 4718592};
    const float* rw2[3] = {wr + 7077888, wr + 7120896, wr + 8300544};
    const float *rwq = wr + 11446272, *rwk = wr + 12036096;
    const float *rwv = wr + 12625920, *rwo = wr + 13215744;
    const float *rmw1 = wr + 13805568, *rmw2 = wr + 16164864;

    cudaFuncSetAttribute(gemm_tc<1,0,1,1>, cudaFuncAttributeMaxDynamicSharedMemorySize, GEMM_SMEM);
    cudaFuncSetAttribute(gemm_tc<0,0,0,0>, cudaFuncAttributeMaxDynamicSharedMemorySize, GEMM_SMEM);
    cudaFuncSetAttribute(gemm_tc_sk<0>,    cudaFuncAttributeMaxDynamicSharedMemorySize, GEMM_SMEM);
    cudaFuncSetAttribute(gemm_tc_sk<1>,    cudaFuncAttributeMaxDynamicSharedMemorySize, GEMM_SMEM);
    cudaFuncSetAttribute(gemm_qkv,         cudaFuncAttributeMaxDynamicSharedMemorySize, GEMM_SMEM);
    cudaFuncSetAttribute(conv_tiled<128>,  cudaFuncAttributeMaxDynamicSharedMemorySize, CONV_SMEM);
    cudaFuncSetAttribute(conv_tiled<256>,  cudaFuncAttributeMaxDynamicSharedMemorySize, CONV_SMEM);
    cudaFuncSetAttribute(attn_mma,         cudaFuncAttributeMaxDynamicSharedMemorySize, ATT_SMEM);

    const int orderF[3] = {14, 384, 1024};
    const int Fs[3]     = {7, 128, 256};
    const int ords[3]   = {2, 3, 4};
    const int skS[3]    = {4, 4, 2};
    const int skKC[3]   = {768, 768, 1536};

    const float* hcur = x;
    float* bufs[2] = {ha, hb};
    int cur = 0;
    const int convBlocks = (ROWS * (Dq/4) + 255) / 256;

    for (int s3 = 0; s3 < 3; s3++) {
        gemm_tc<1,0,1,1><<<dim3(24,32), 256, GEMM_SMEM>>>(hcur, rw1[s3], b1s[s3], nullptr, t1, 3072, 768);
        cudaMemsetAsync(pp, 0, sizeof(float)*(size_t)ROWS*orderF[s3]);
        gemm_tc_sk<0><<<dim3((orderF[s3]+127)/128, 32, skS[s3]), 256, GEMM_SMEM>>>(
            t1, rw2[s3], b2s[s3], nullptr, pp, orderF[s3], 3072, skKC[s3]);
        for (int i = 0; i < ords[s3]; i++) {
            if (Fs[s3] == 7)
                conv_gelu<<<convBlocks, 256>>>(hcur, pp, bufs[cur], 7, orderF[s3], i * 7);
            else if (Fs[s3] == 128)
                conv_tiled<128><<<dim3(12,64), 256, CONV_SMEM>>>(hcur, pp, bufs[cur], orderF[s3], i * 128);
            else
                conv_tiled<256><<<dim3(12,64), 256, CONV_SMEM>>>(hcur, pp, bufs[cur], orderF[s3], i * 256);
            hcur = bufs[cur];
            cur ^= 1;
        }
    }

    ln_rope_kernel<<<ROWS, 256>>>(x, hcur, ln1g, ln1b, sn, cs, gx, gqk);

    gemm_qkv<<<dim3(6,32,3), 256, GEMM_SMEM>>>(gqk, gx, rwq, bqv, gq, rwk, bkv, gk, rwv, bvv, gv);

    attn_mma<<<dim3(Lq/64, Bq*Hq), 128, ATT_SMEM>>>(gq, gk, gv, gatt);

    gemm_tc<0,0,0,0><<<dim3(6,32), 256, GEMM_SMEM>>>(gatt, rwo, bov, nullptr, go, 768, 768);
    ln_kernel<<<ROWS, 256>>>(gx, go, ln2g, ln2b, gx2);
    gemm_tc<1,0,1,1><<<dim3(24,32), 256, GEMM_SMEM>>>(gx2, rmw1, mb1, nullptr, t1, 3072, 768);
    cudaMemsetAsync(d_out, 0, sizeof(float)*(size_t)ROWS*768);
    gemm_tc_sk<1><<<dim3(6,32,2), 256, GEMM_SMEM>>>(
        t1, rmw2, mb2, gx2, (float*)d_out, 768, 3072, 1536);
}